// round 9
// baseline (speedup 1.0000x reference)
#include <cuda_runtime.h>
#include <cuda_fp16.h>
#include <cstdint>
#include <cstddef>

// Problem constants
#define BB 4
#define TT 2048
#define CC 1024
#define HH 16
#define DK 64
#define BT (BB*TT)        // 8192
#define C3 (3*CC)         // 3072

// ---------------------------------------------------------------------------
// Scratch (allocation-free rule: device globals) — fp16 split pairs
// ---------------------------------------------------------------------------
__device__ __half g_xh[(size_t)BT * CC],  g_xl[(size_t)BT * CC];
__device__ __half g_wqh[(size_t)C3 * CC], g_wql[(size_t)C3 * CC];
__device__ __half g_woh[(size_t)CC * CC], g_wol[(size_t)CC * CC];
// pre-split attention operands, ALL natural [t][d] layout (GEMM1 epilogue)
__device__ __half g_qh[(size_t)BT * CC],  g_ql[(size_t)BT * CC];   // q: pre-scaled
__device__ __half g_kh[(size_t)BT * CC],  g_kl[(size_t)BT * CC];
__device__ __half g_vh[(size_t)BT * CC],  g_vl[(size_t)BT * CC];
// attention output, split (input of GEMM2)
__device__ __half g_ah[(size_t)BT * CC],  g_al[(size_t)BT * CC];

extern __shared__ char dynsm[];

__device__ __forceinline__ uint32_t smem_to_u32(const void* p) {
    uint32_t a;
    asm("{ .reg .u64 t; cvta.to.shared.u64 t, %1; cvt.u32.u64 %0, t; }"
        : "=r"(a) : "l"(p));
    return a;
}
__device__ __forceinline__ void mma_f16(float* c, const uint32_t* a, const uint32_t* b) {
    asm volatile("mma.sync.aligned.m16n8k16.row.col.f32.f16.f16.f32 "
        "{%0,%1,%2,%3}, {%4,%5,%6,%7}, {%8,%9}, {%0,%1,%2,%3};"
        : "+f"(c[0]), "+f"(c[1]), "+f"(c[2]), "+f"(c[3])
        : "r"(a[0]), "r"(a[1]), "r"(a[2]), "r"(a[3]), "r"(b[0]), "r"(b[1]));
}
__device__ __forceinline__ void ldsm_x4(uint32_t* r, uint32_t addr) {
    asm volatile("ldmatrix.sync.aligned.m8n8.x4.shared.b16 {%0,%1,%2,%3}, [%4];"
        : "=r"(r[0]), "=r"(r[1]), "=r"(r[2]), "=r"(r[3]) : "r"(addr));
}
__device__ __forceinline__ void ldsm_x2(uint32_t* r, uint32_t addr) {
    asm volatile("ldmatrix.sync.aligned.m8n8.x2.shared.b16 {%0,%1}, [%2];"
        : "=r"(r[0]), "=r"(r[1]) : "r"(addr));
}
__device__ __forceinline__ void ldsm_x2_trans(uint32_t* r, uint32_t addr) {
    asm volatile("ldmatrix.sync.aligned.m8n8.x2.trans.shared.b16 {%0,%1}, [%2];"
        : "=r"(r[0]), "=r"(r[1]) : "r"(addr));
}
#define CP_ASYNC16(dst, src) \
    asm volatile("cp.async.cg.shared.global [%0], [%1], 16;" :: "r"(dst), "l"(src))
#define CP_COMMIT()  asm volatile("cp.async.commit_group;" ::: "memory")
#define CP_WAIT1()   asm volatile("cp.async.wait_group 1;" ::: "memory")

// fp16 hi/lo split: hi = fp16(x), lo = fp16(x - hi)  (captures ~22 mantissa bits)
__device__ __forceinline__ void split2(float a, float b, uint32_t& h, uint32_t& l) {
    __half ha = __float2half_rn(a), hb = __float2half_rn(b);
    __half la = __float2half_rn(a - __half2float(ha));
    __half lb = __float2half_rn(b - __half2float(hb));
    __half2 hp = __halves2half2(ha, hb);
    __half2 lp = __halves2half2(la, lb);
    h = *(uint32_t*)&hp; l = *(uint32_t*)&lp;
}

// ---------------------------------------------------------------------------
// Split-fp16 conversion kernel (inputs x, Wqkv, Wo)
// ---------------------------------------------------------------------------
__global__ void cvt_split_kernel(const float4* __restrict__ src,
                                 __half2* __restrict__ hi,
                                 __half2* __restrict__ lo, int n4)
{
    int i = blockIdx.x * blockDim.x + threadIdx.x;
    if (i >= n4) return;
    float4 v = src[i];
    uint32_t h0, h1, l0, l1;
    split2(v.x, v.y, h0, l0);
    split2(v.z, v.w, h1, l1);
    hi[2*i] = *(__half2*)&h0; hi[2*i+1] = *(__half2*)&h1;
    lo[2*i] = *(__half2*)&l0; lo[2*i+1] = *(__half2*)&l1;
}

// ---------------------------------------------------------------------------
// HMMA split-fp16 GEMM — 512 threads, 3-stage cp.async, product-major MMA order.
// MODE 0: C fp32.  MODE 1: qkv epilogue, all-coalesced split stores.
// ---------------------------------------------------------------------------
#define RS_B    80
#define TILE_B  (128*RS_B)          // 10240
#define STAGE_B (4*TILE_B)          // 40960
#define STAGES  3
#define GEMM_SMEM (STAGES*STAGE_B)  // 122880

template<int MODE>
__global__ __launch_bounds__(512, 1) void gemm_f16x3_kernel(
    const __half* __restrict__ Ah, const __half* __restrict__ Al,
    const __half* __restrict__ Bh, const __half* __restrict__ Bl,
    float* __restrict__ C, int M, int N, int K)
{
    const int tid = threadIdx.x, lane = tid & 31, wid = tid >> 5;
    const int bm = blockIdx.y * 128, bn = blockIdx.x * 128;
    const int wr = wid >> 2, wc = wid & 3;     // 4x4 warp grid, 32x32 tiles
    const uint32_t sbase = smem_to_u32(dynsm);
    const int NC = K / 32;

    float acc[2][4][4];
#pragma unroll
    for (int i = 0; i < 2; i++)
#pragma unroll
        for (int j = 0; j < 4; j++)
#pragma unroll
            for (int v = 0; v < 4; v++) acc[i][j][v] = 0.0f;

    auto load_stage = [&](int st, int buf) {
        const int kk = st * 32;
        const uint32_t dstb = sbase + buf * STAGE_B;
#pragma unroll
        for (int i = 0; i < 4; i++) {
            int c = tid + i * 512;                 // 0..2047
            int tile = c >> 9;
            int rc = c & 511;
            int row = rc >> 2, kc = rc & 3;
            const __half* src;
            if (tile == 0)      src = Ah + (size_t)(bm + row) * K + kk + kc * 8;
            else if (tile == 1) src = Al + (size_t)(bm + row) * K + kk + kc * 8;
            else if (tile == 2) src = Bh + (size_t)(bn + row) * K + kk + kc * 8;
            else                src = Bl + (size_t)(bn + row) * K + kk + kc * 8;
            uint32_t dst = dstb + tile * TILE_B + row * RS_B + kc * 16;
            CP_ASYNC16(dst, src);
        }
    };

    const uint32_t a_off0 = (wr * 32 + (lane & 15)) * RS_B + (lane >> 4) * 16;
    const uint32_t b_off0 = (wc * 32 + (lane & 7)) * RS_B + ((lane >> 3) & 1) * 16;

    load_stage(0, 0); CP_COMMIT();
    load_stage(1, 1); CP_COMMIT();

    for (int it = 0; it < NC; it++) {
        CP_WAIT1();
        __syncthreads();
        const int nxt = it + (STAGES - 1);
        if (nxt < NC) load_stage(nxt, nxt % STAGES);
        CP_COMMIT();

        const uint32_t tb = sbase + (it % STAGES) * STAGE_B;
#pragma unroll
        for (int ks = 0; ks < 2; ks++) {
            uint32_t ah[2][4], al[2][4], bh[4][2], bl[4][2];
#pragma unroll
            for (int mt = 0; mt < 2; mt++) {
                uint32_t aaddr = tb + a_off0 + mt * (16 * RS_B) + ks * 32;
                ldsm_x4(ah[mt], aaddr);
                ldsm_x4(al[mt], aaddr + TILE_B);
            }
#pragma unroll
            for (int nt = 0; nt < 4; nt++) {
                uint32_t baddr = tb + 2 * TILE_B + b_off0 + nt * (8 * RS_B) + ks * 32;
                ldsm_x2(bh[nt], baddr);
                ldsm_x2(bl[nt], baddr + TILE_B);
            }
            // product-major: same-acc MMAs spaced by 8
#pragma unroll
            for (int mt = 0; mt < 2; mt++)
#pragma unroll
                for (int nt = 0; nt < 4; nt++) mma_f16(acc[mt][nt], ah[mt], bh[nt]);
#pragma unroll
            for (int mt = 0; mt < 2; mt++)
#pragma unroll
                for (int nt = 0; nt < 4; nt++) mma_f16(acc[mt][nt], al[mt], bh[nt]);
#pragma unroll
            for (int mt = 0; mt < 2; mt++)
#pragma unroll
                for (int nt = 0; nt < 4; nt++) mma_f16(acc[mt][nt], ah[mt], bl[nt]);
        }
    }

    // epilogue
    const int g = lane >> 2, t = lane & 3;
#pragma unroll
    for (int mt = 0; mt < 2; mt++) {
#pragma unroll
        for (int nt = 0; nt < 4; nt++) {
            int row = bm + wr * 32 + mt * 16 + g;
            int col = bn + wc * 32 + nt * 8 + t * 2;
            if (MODE == 0) {
                *(float2*)&C[(size_t)row * N + col] =
                    make_float2(acc[mt][nt][0], acc[mt][nt][1]);
                *(float2*)&C[(size_t)(row + 8) * N + col] =
                    make_float2(acc[mt][nt][2], acc[mt][nt][3]);
            } else {
                float s = (bn < CC) ? 0.125f : 1.0f;     // q pre-scaled
                __half *dh, *dl;
                int cc;
                if (bn < CC)            { dh = g_qh; dl = g_ql; cc = col; }
                else if (bn < 2 * CC)   { dh = g_kh; dl = g_kl; cc = col - CC; }
                else                    { dh = g_vh; dl = g_vl; cc = col - 2 * CC; }
                uint32_t h0, l0, h1, l1;
                split2(acc[mt][nt][0] * s, acc[mt][nt][1] * s, h0, l0);
                split2(acc[mt][nt][2] * s, acc[mt][nt][3] * s, h1, l1);
                *(uint32_t*)&dh[(size_t)row * CC + cc]       = h0;
                *(uint32_t*)&dl[(size_t)row * CC + cc]       = l0;
                *(uint32_t*)&dh[(size_t)(row + 8) * CC + cc] = h1;
                *(uint32_t*)&dl[(size_t)(row + 8) * CC + cc] = l1;
            }
        }
    }
}

// ---------------------------------------------------------------------------
// HMMA split-fp16 flash attention, causal. Product-major MMA order.
// ---------------------------------------------------------------------------
#define RSA   144
#define QREG  18432                 // 128*144
#define SBUF  (2*QREG)              // 36864
#define SSZ   36864                 // KH,KL,VH,VL @ 9216 each
#define ATT_SMEM (SBUF + 2*SSZ)     // 110592

__global__ __launch_bounds__(256, 1) void attn_mma_kernel()
{
    const uint32_t sbase = smem_to_u32(dynsm);
    const int tid = threadIdx.x, lane = tid & 31, w = tid >> 5;
    const int qb = blockIdx.x;
    const int b  = blockIdx.y >> 4;
    const int h  = blockIdx.y & 15;
    const size_t rbase = (size_t)b * TT;
    const int coff = h * DK;
    const int g = lane >> 2, t = lane & 3;

    // ---- stage Q (hi+lo) via cp.async ----
#pragma unroll
    for (int i = 0; i < 8; i++) {
        int idx = tid + i * 256;              // 0..2047
        int arr = idx >> 10;                  // 0: qh, 1: ql
        int rem = idx & 1023;
        int r = rem >> 3, c = rem & 7;
        const __half* src =
            (arr ? g_ql : g_qh) + (rbase + (size_t)qb * 128 + r) * CC + coff + c * 8;
        uint32_t dst = sbase + arr * QREG + r * RSA + c * 16;
        CP_ASYNC16(dst, src);
    }

    auto load_stage = [&](int jb, int s) {
        const uint32_t dstb = sbase + SBUF + s * SSZ;
#pragma unroll
        for (int i = 0; i < 8; i++) {
            int idx = tid + i * 256;          // 0..2047
            int sub = idx >> 9;               // 0:KH 1:KL 2:VH 3:VL
            int rem = idx & 511;
            int r = rem >> 3, c = rem & 7;
            const __half* base;
            if (sub == 0)      base = g_kh;
            else if (sub == 1) base = g_kl;
            else if (sub == 2) base = g_vh;
            else               base = g_vl;
            const __half* src = base + (rbase + (size_t)jb * 64 + r) * CC + coff + c * 8;
            uint32_t dst = dstb + sub * 9216 + r * RSA + c * 16;
            CP_ASYNC16(dst, src);
        }
    };

    const int jb_end = 2 * qb + 1;
    load_stage(0, 0);
    CP_COMMIT();            // group: Q + stage0

    float oacc[8][4];
#pragma unroll
    for (int n = 0; n < 8; n++)
#pragma unroll
        for (int v = 0; v < 4; v++) oacc[n][v] = 0.0f;
    float m0 = -1e30f, m1 = -1e30f, l0s = 0.0f, l1s = 0.0f;
    uint32_t qh[4][4], ql[4][4];

    const int qrow0 = qb * 128 + w * 16 + g;

    for (int jb = 0; jb <= jb_end; jb++) {
        const int buf = jb & 1;
        if (jb + 1 <= jb_end) load_stage(jb + 1, buf ^ 1);
        CP_COMMIT();
        CP_WAIT1();
        __syncthreads();

        if (jb == 0) {   // Q fragments (once)
#pragma unroll
            for (int kt = 0; kt < 4; kt++) {
                uint32_t addr = sbase + (w * 16 + (lane & 15)) * RSA
                              + (lane >> 4) * 16 + kt * 32;
                ldsm_x4(qh[kt], addr);
                ldsm_x4(ql[kt], addr + QREG);
            }
        }

        const uint32_t KhB = sbase + SBUF + buf * SSZ;
        const uint32_t KlB = KhB + 9216;
        const uint32_t VhB = KhB + 18432;
        const uint32_t VlB = KhB + 27648;

        const bool active = (jb * 64 <= qb * 128 + w * 16 + 15);
        if (active) {
            // ---- S = Q K^T (3 products, product-major per kt) ----
            float sacc[8][4];
#pragma unroll
            for (int n = 0; n < 8; n++)
#pragma unroll
                for (int v = 0; v < 4; v++) sacc[n][v] = 0.0f;
#pragma unroll
            for (int kt = 0; kt < 4; kt++) {
                uint32_t bh[8][2], bl[8][2];
#pragma unroll
                for (int n = 0; n < 8; n++) {
                    uint32_t baddr = (n * 8 + (lane & 7)) * RSA + kt * 32
                                   + ((lane >> 3) & 1) * 16;
                    ldsm_x2(bh[n], KhB + baddr);
                    ldsm_x2(bl[n], KlB + baddr);
                }
#pragma unroll
                for (int n = 0; n < 8; n++) mma_f16(sacc[n], qh[kt], bh[n]);
#pragma unroll
                for (int n = 0; n < 8; n++) mma_f16(sacc[n], ql[kt], bh[n]);
#pragma unroll
                for (int n = 0; n < 8; n++) mma_f16(sacc[n], qh[kt], bl[n]);
            }

            // ---- causal mask ----
            if (jb * 64 + 63 > qrow0) {
#pragma unroll
                for (int n = 0; n < 8; n++) {
                    int colb = jb * 64 + n * 8 + t * 2;
                    if (colb     > qrow0)     sacc[n][0] = -1e30f;
                    if (colb + 1 > qrow0)     sacc[n][1] = -1e30f;
                    if (colb     > qrow0 + 8) sacc[n][2] = -1e30f;
                    if (colb + 1 > qrow0 + 8) sacc[n][3] = -1e30f;
                }
            }

            // ---- online softmax ----
            float rmax0 = -1e30f, rmax1 = -1e30f;
#pragma unroll
            for (int n = 0; n < 8; n++) {
                rmax0 = fmaxf(rmax0, fmaxf(sacc[n][0], sacc[n][1]));
                rmax1 = fmaxf(rmax1, fmaxf(sacc[n][2], sacc[n][3]));
            }
            rmax0 = fmaxf(rmax0, __shfl_xor_sync(0xffffffffu, rmax0, 1));
            rmax0 = fmaxf(rmax0, __shfl_xor_sync(0xffffffffu, rmax0, 2));
            rmax1 = fmaxf(rmax1, __shfl_xor_sync(0xffffffffu, rmax1, 1));
            rmax1 = fmaxf(rmax1, __shfl_xor_sync(0xffffffffu, rmax1, 2));

            const float mn0 = fmaxf(m0, rmax0), mn1 = fmaxf(m1, rmax1);
            const float c0 = __expf(m0 - mn0), c1 = __expf(m1 - mn1);
            float rs0 = 0.0f, rs1 = 0.0f;
#pragma unroll
            for (int n = 0; n < 8; n++) {
                sacc[n][0] = __expf(sacc[n][0] - mn0);
                sacc[n][1] = __expf(sacc[n][1] - mn0);
                sacc[n][2] = __expf(sacc[n][2] - mn1);
                sacc[n][3] = __expf(sacc[n][3] - mn1);
                rs0 += sacc[n][0] + sacc[n][1];
                rs1 += sacc[n][2] + sacc[n][3];
            }
            rs0 += __shfl_xor_sync(0xffffffffu, rs0, 1);
            rs0 += __shfl_xor_sync(0xffffffffu, rs0, 2);
            rs1 += __shfl_xor_sync(0xffffffffu, rs1, 1);
            rs1 += __shfl_xor_sync(0xffffffffu, rs1, 2);
            l0s = l0s * c0 + rs0; l1s = l1s * c1 + rs1;
            m0 = mn0; m1 = mn1;
#pragma unroll
            for (int n = 0; n < 8; n++) {
                oacc[n][0] *= c0; oacc[n][1] *= c0;
                oacc[n][2] *= c1; oacc[n][3] *= c1;
            }

            // ---- O += P V (3 products, product-major per kt); V via trans-ldsm ----
#pragma unroll
            for (int kt = 0; kt < 4; kt++) {
                uint32_t pah[4], pal[4];
                split2(sacc[2*kt][0],   sacc[2*kt][1],   pah[0], pal[0]);
                split2(sacc[2*kt][2],   sacc[2*kt][3],   pah[1], pal[1]);
                split2(sacc[2*kt+1][0], sacc[2*kt+1][1], pah[2], pal[2]);
                split2(sacc[2*kt+1][2], sacc[2*kt+1][3], pah[3], pal[3]);
                const uint32_t vrow = (kt * 16 + (lane & 15)) * RSA;
                uint32_t bvh[8][2], bvl[8][2];
#pragma unroll
                for (int n = 0; n < 8; n++) {
                    uint32_t baddr = vrow + n * 16;
                    ldsm_x2_trans(bvh[n], VhB + baddr);
                    ldsm_x2_trans(bvl[n], VlB + baddr);
                }
#pragma unroll
                for (int n = 0; n < 8; n++) mma_f16(oacc[n], pah, bvh[n]);
#pragma unroll
                for (int n = 0; n < 8; n++) mma_f16(oacc[n], pal, bvh[n]);
#pragma unroll
                for (int n = 0; n < 8; n++) mma_f16(oacc[n], pah, bvl[n]);
            }
        }
        __syncthreads();   // buffer consumed before next prefetch overwrites
    }

    // ---- epilogue: normalize, split, store fp16 hi/lo ----
    const float inv0 = 1.0f / l0s, inv1 = 1.0f / l1s;
    const size_t r0 = rbase + (size_t)qb * 128 + w * 16 + g;
#pragma unroll
    for (int n = 0; n < 8; n++) {
        int col = coff + n * 8 + t * 2;
        uint32_t h0, l0, h1, l1;
        split2(oacc[n][0] * inv0, oacc[n][1] * inv0, h0, l0);
        split2(oacc[n][2] * inv1, oacc[n][3] * inv1, h1, l1);
        *(uint32_t*)&g_ah[r0 * CC + col]       = h0;
        *(uint32_t*)&g_al[r0 * CC + col]       = l0;
        *(uint32_t*)&g_ah[(r0 + 8) * CC + col] = h1;
        *(uint32_t*)&g_al[(r0 + 8) * CC + col] = l1;
    }
}

// ---------------------------------------------------------------------------
extern "C" void kernel_launch(void* const* d_in, const int* in_sizes, int n_in,
                              void* d_out, int out_size)
{
    const float* x    = (const float*)d_in[0];
    const float* Wqkv = (const float*)d_in[1];
    const float* Wo   = (const float*)d_in[2];
    float* out        = (float*)d_out;

    __half *xh, *xl, *wqh, *wql, *woh, *wol, *ah, *al;
    cudaGetSymbolAddress((void**)&xh, g_xh);   cudaGetSymbolAddress((void**)&xl, g_xl);
    cudaGetSymbolAddress((void**)&wqh, g_wqh); cudaGetSymbolAddress((void**)&wql, g_wql);
    cudaGetSymbolAddress((void**)&woh, g_woh); cudaGetSymbolAddress((void**)&wol, g_wol);
    cudaGetSymbolAddress((void**)&ah, g_ah);   cudaGetSymbolAddress((void**)&al, g_al);

    cudaFuncSetAttribute(gemm_f16x3_kernel<0>,
                         cudaFuncAttributeMaxDynamicSharedMemorySize, GEMM_SMEM);
    cudaFuncSetAttribute(gemm_f16x3_kernel<1>,
                         cudaFuncAttributeMaxDynamicSharedMemorySize, GEMM_SMEM);
    cudaFuncSetAttribute(attn_mma_kernel,
                         cudaFuncAttributeMaxDynamicSharedMemorySize, ATT_SMEM);

    // split-fp16 conversions (inputs only)
    {
        int n4 = BT * CC / 4;
        cvt_split_kernel<<<(n4 + 255)/256, 256>>>((const float4*)x,
            (__half2*)xh, (__half2*)xl, n4);
        n4 = C3 * CC / 4;
        cvt_split_kernel<<<(n4 + 255)/256, 256>>>((const float4*)Wqkv,
            (__half2*)wqh, (__half2*)wql, n4);
        n4 = CC * CC / 4;
        cvt_split_kernel<<<(n4 + 255)/256, 256>>>((const float4*)Wo,
            (__half2*)woh, (__half2*)wol, n4);
    }

    // 1) qkv projection; epilogue emits pre-split q(scaled)/k/v, natural layout
    {
        dim3 grid(C3 / 128, BT / 128);
        gemm_f16x3_kernel<1><<<grid, 512, GEMM_SMEM>>>(
            xh, xl, wqh, wql, (float*)nullptr, BT, C3, CC);
    }
    // 2) causal flash attention (HMMA split-fp16)
    {
        dim3 grid(TT / 128, BB * HH);
        attn_mma_kernel<<<grid, 256, ATT_SMEM>>>();
    }
    // 3) out = att @ Wo^T (fp32 result)
    {
        dim3 grid(CC / 128, BT / 128);
        gemm_f16x3_kernel<0><<<grid, 512, GEMM_SMEM>>>(
            ah, al, woh, wol, out, BT, CC, CC);
    }
}

// round 10
// speedup vs baseline: 1.0356x; 1.0356x over previous
#include <cuda_runtime.h>
#include <cuda_fp16.h>
#include <cstdint>
#include <cstddef>

// Problem constants
#define BB 4
#define TT 2048
#define CC 1024
#define HH 16
#define DK 64
#define BT (BB*TT)        // 8192
#define C3 (3*CC)         // 3072

// ---------------------------------------------------------------------------
// Scratch (allocation-free rule: device globals) — fp16 split pairs
// ---------------------------------------------------------------------------
__device__ __half g_xh[(size_t)BT * CC],  g_xl[(size_t)BT * CC];
__device__ __half g_wqh[(size_t)C3 * CC], g_wql[(size_t)C3 * CC];
__device__ __half g_woh[(size_t)CC * CC], g_wol[(size_t)CC * CC];
// pre-split attention operands, ALL natural [t][d] layout (GEMM1 epilogue)
__device__ __half g_qh[(size_t)BT * CC],  g_ql[(size_t)BT * CC];   // q: pre-scaled
__device__ __half g_kh[(size_t)BT * CC],  g_kl[(size_t)BT * CC];
__device__ __half g_vh[(size_t)BT * CC],  g_vl[(size_t)BT * CC];
// attention output, split (input of GEMM2)
__device__ __half g_ah[(size_t)BT * CC],  g_al[(size_t)BT * CC];

extern __shared__ char dynsm[];

__device__ __forceinline__ uint32_t smem_to_u32(const void* p) {
    uint32_t a;
    asm("{ .reg .u64 t; cvta.to.shared.u64 t, %1; cvt.u32.u64 %0, t; }"
        : "=r"(a) : "l"(p));
    return a;
}
__device__ __forceinline__ void mma_f16(float* c, const uint32_t* a, const uint32_t* b) {
    asm volatile("mma.sync.aligned.m16n8k16.row.col.f32.f16.f16.f32 "
        "{%0,%1,%2,%3}, {%4,%5,%6,%7}, {%8,%9}, {%0,%1,%2,%3};"
        : "+f"(c[0]), "+f"(c[1]), "+f"(c[2]), "+f"(c[3])
        : "r"(a[0]), "r"(a[1]), "r"(a[2]), "r"(a[3]), "r"(b[0]), "r"(b[1]));
}
__device__ __forceinline__ void ldsm_x4(uint32_t* r, uint32_t addr) {
    asm volatile("ldmatrix.sync.aligned.m8n8.x4.shared.b16 {%0,%1,%2,%3}, [%4];"
        : "=r"(r[0]), "=r"(r[1]), "=r"(r[2]), "=r"(r[3]) : "r"(addr));
}
__device__ __forceinline__ void ldsm_x2(uint32_t* r, uint32_t addr) {
    asm volatile("ldmatrix.sync.aligned.m8n8.x2.shared.b16 {%0,%1}, [%2];"
        : "=r"(r[0]), "=r"(r[1]) : "r"(addr));
}
__device__ __forceinline__ void ldsm_x2_trans(uint32_t* r, uint32_t addr) {
    asm volatile("ldmatrix.sync.aligned.m8n8.x2.trans.shared.b16 {%0,%1}, [%2];"
        : "=r"(r[0]), "=r"(r[1]) : "r"(addr));
}
#define CP_ASYNC16(dst, src) \
    asm volatile("cp.async.cg.shared.global [%0], [%1], 16;" :: "r"(dst), "l"(src))
#define CP_COMMIT()  asm volatile("cp.async.commit_group;" ::: "memory")
#define CP_WAIT1()   asm volatile("cp.async.wait_group 1;" ::: "memory")

// fp16 hi/lo split: hi = fp16(x), lo = fp16(x - hi)
__device__ __forceinline__ void split2(float a, float b, uint32_t& h, uint32_t& l) {
    __half ha = __float2half_rn(a), hb = __float2half_rn(b);
    __half la = __float2half_rn(a - __half2float(ha));
    __half lb = __float2half_rn(b - __half2float(hb));
    __half2 hp = __halves2half2(ha, hb);
    __half2 lp = __halves2half2(la, lb);
    h = *(uint32_t*)&hp; l = *(uint32_t*)&lp;
}

// ---------------------------------------------------------------------------
// Merged split-fp16 conversion: x | Wqkv | Wo in one launch
// ---------------------------------------------------------------------------
#define N4_X   (BT * CC / 4)      // 2097152
#define N4_WQ  (C3 * CC / 4)      // 786432
#define N4_WO  (CC * CC / 4)      // 262144
#define N4_ALL (N4_X + N4_WQ + N4_WO)

__global__ void cvt_split_all_kernel(const float4* __restrict__ x,
                                     const float4* __restrict__ wq,
                                     const float4* __restrict__ wo)
{
    int i = blockIdx.x * blockDim.x + threadIdx.x;
    if (i >= N4_ALL) return;
    const float4* src;
    __half2 *hi, *lo;
    int j;
    if (i < N4_X) {
        j = i;            src = x;  hi = (__half2*)g_xh;  lo = (__half2*)g_xl;
    } else if (i < N4_X + N4_WQ) {
        j = i - N4_X;     src = wq; hi = (__half2*)g_wqh; lo = (__half2*)g_wql;
    } else {
        j = i - N4_X - N4_WQ; src = wo; hi = (__half2*)g_woh; lo = (__half2*)g_wol;
    }
    float4 v = src[j];
    uint32_t h0, h1, l0, l1;
    split2(v.x, v.y, h0, l0);
    split2(v.z, v.w, h1, l1);
    hi[2*j] = *(__half2*)&h0; hi[2*j+1] = *(__half2*)&h1;
    lo[2*j] = *(__half2*)&l0; lo[2*j+1] = *(__half2*)&l1;
}

// ---------------------------------------------------------------------------
// HMMA split-fp16 GEMM — CTA tile 128x64, 8 warps (32x32), 3-stage cp.async,
// 2 CTAs/SM. Product-major MMA order.
// MODE 0: C fp32.  MODE 1: qkv epilogue, all-coalesced split stores.
// ---------------------------------------------------------------------------
#define RS_B     80
#define A_TILE_B (128*RS_B)         // 10240
#define B_TILE_B (64*RS_B)          // 5120
#define STAGE_B  (2*A_TILE_B + 2*B_TILE_B)   // 30720
#define STAGES   3
#define GEMM_SMEM (STAGES*STAGE_B)  // 92160  (x2 CTAs = 184320 <= 228KB)

template<int MODE>
__global__ __launch_bounds__(256, 2) void gemm_f16x3_kernel(
    const __half* __restrict__ Ah, const __half* __restrict__ Al,
    const __half* __restrict__ Bh, const __half* __restrict__ Bl,
    float* __restrict__ C, int M, int N, int K)
{
    const int tid = threadIdx.x, lane = tid & 31, wid = tid >> 5;
    const int bm = blockIdx.y * 128, bn = blockIdx.x * 64;
    const int wr = wid >> 1, wc = wid & 1;     // 4x2 warp grid, 32x32 tiles
    const uint32_t sbase = smem_to_u32(dynsm);
    const int NC = K / 32;

    float acc[2][4][4];
#pragma unroll
    for (int i = 0; i < 2; i++)
#pragma unroll
        for (int j = 0; j < 4; j++)
#pragma unroll
            for (int v = 0; v < 4; v++) acc[i][j][v] = 0.0f;

    // 1536 16B-chunks per stage: A(h,l) 2x512, B(h,l) 2x256. 6 per thread.
    auto load_stage = [&](int st, int buf) {
        const int kk = st * 32;
        const uint32_t dstb = sbase + buf * STAGE_B;
#pragma unroll
        for (int i = 0; i < 6; i++) {
            int c = tid + i * 256;                 // 0..1535
            const __half* src;
            uint32_t dst;
            if (c < 1024) {
                int arr = c >> 9, rc = c & 511;
                int row = rc >> 2, kc = rc & 3;
                src = (arr ? Al : Ah) + (size_t)(bm + row) * K + kk + kc * 8;
                dst = dstb + arr * A_TILE_B + row * RS_B + kc * 16;
            } else {
                int cb = c - 1024;
                int arr = cb >> 8, rc = cb & 255;
                int row = rc >> 2, kc = rc & 3;
                src = (arr ? Bl : Bh) + (size_t)(bn + row) * K + kk + kc * 8;
                dst = dstb + 2 * A_TILE_B + arr * B_TILE_B + row * RS_B + kc * 16;
            }
            CP_ASYNC16(dst, src);
        }
    };

    const uint32_t a_off0 = (wr * 32 + (lane & 15)) * RS_B + (lane >> 4) * 16;
    const uint32_t b_off0 = (wc * 32 + (lane & 7)) * RS_B + ((lane >> 3) & 1) * 16;

    load_stage(0, 0); CP_COMMIT();
    load_stage(1, 1); CP_COMMIT();

    for (int it = 0; it < NC; it++) {
        CP_WAIT1();
        __syncthreads();
        const int nxt = it + (STAGES - 1);
        if (nxt < NC) load_stage(nxt, nxt % STAGES);
        CP_COMMIT();

        const uint32_t tb = sbase + (it % STAGES) * STAGE_B;
#pragma unroll
        for (int ks = 0; ks < 2; ks++) {
            uint32_t ah[2][4], al[2][4], bh[4][2], bl[4][2];
#pragma unroll
            for (int mt = 0; mt < 2; mt++) {
                uint32_t aaddr = tb + a_off0 + mt * (16 * RS_B) + ks * 32;
                ldsm_x4(ah[mt], aaddr);
                ldsm_x4(al[mt], aaddr + A_TILE_B);
            }
#pragma unroll
            for (int nt = 0; nt < 4; nt++) {
                uint32_t baddr = tb + 2 * A_TILE_B + b_off0 + nt * (8 * RS_B) + ks * 32;
                ldsm_x2(bh[nt], baddr);
                ldsm_x2(bl[nt], baddr + B_TILE_B);
            }
            // product-major: same-acc MMAs spaced by 8
#pragma unroll
            for (int mt = 0; mt < 2; mt++)
#pragma unroll
                for (int nt = 0; nt < 4; nt++) mma_f16(acc[mt][nt], ah[mt], bh[nt]);
#pragma unroll
            for (int mt = 0; mt < 2; mt++)
#pragma unroll
                for (int nt = 0; nt < 4; nt++) mma_f16(acc[mt][nt], al[mt], bh[nt]);
#pragma unroll
            for (int mt = 0; mt < 2; mt++)
#pragma unroll
                for (int nt = 0; nt < 4; nt++) mma_f16(acc[mt][nt], ah[mt], bl[nt]);
        }
    }

    // epilogue
    const int g = lane >> 2, t = lane & 3;
#pragma unroll
    for (int mt = 0; mt < 2; mt++) {
#pragma unroll
        for (int nt = 0; nt < 4; nt++) {
            int row = bm + wr * 32 + mt * 16 + g;
            int col = bn + wc * 32 + nt * 8 + t * 2;
            if (MODE == 0) {
                *(float2*)&C[(size_t)row * N + col] =
                    make_float2(acc[mt][nt][0], acc[mt][nt][1]);
                *(float2*)&C[(size_t)(row + 8) * N + col] =
                    make_float2(acc[mt][nt][2], acc[mt][nt][3]);
            } else {
                float s = (bn < CC) ? 0.125f : 1.0f;     // q pre-scaled
                __half *dh, *dl;
                int cc;
                if (bn < CC)            { dh = g_qh; dl = g_ql; cc = col; }
                else if (bn < 2 * CC)   { dh = g_kh; dl = g_kl; cc = col - CC; }
                else                    { dh = g_vh; dl = g_vl; cc = col - 2 * CC; }
                uint32_t h0, l0, h1, l1;
                split2(acc[mt][nt][0] * s, acc[mt][nt][1] * s, h0, l0);
                split2(acc[mt][nt][2] * s, acc[mt][nt][3] * s, h1, l1);
                *(uint32_t*)&dh[(size_t)row * CC + cc]       = h0;
                *(uint32_t*)&dl[(size_t)row * CC + cc]       = l0;
                *(uint32_t*)&dh[(size_t)(row + 8) * CC + cc] = h1;
                *(uint32_t*)&dl[(size_t)(row + 8) * CC + cc] = l1;
            }
        }
    }
}

// ---------------------------------------------------------------------------
// HMMA split-fp16 flash attention, causal (unchanged from R9).
// ---------------------------------------------------------------------------
#define RSA   144
#define QREG  18432                 // 128*144
#define SBUF  (2*QREG)              // 36864
#define SSZ   36864                 // KH,KL,VH,VL @ 9216 each
#define ATT_SMEM (SBUF + 2*SSZ)     // 110592

__global__ __launch_bounds__(256, 1) void attn_mma_kernel()
{
    const uint32_t sbase = smem_to_u32(dynsm);
    const int tid = threadIdx.x, lane = tid & 31, w = tid >> 5;
    const int qb = blockIdx.x;
    const int b  = blockIdx.y >> 4;
    const int h  = blockIdx.y & 15;
    const size_t rbase = (size_t)b * TT;
    const int coff = h * DK;
    const int g = lane >> 2, t = lane & 3;

    // ---- stage Q (hi+lo) via cp.async ----
#pragma unroll
    for (int i = 0; i < 8; i++) {
        int idx = tid + i * 256;              // 0..2047
        int arr = idx >> 10;                  // 0: qh, 1: ql
        int rem = idx & 1023;
        int r = rem >> 3, c = rem & 7;
        const __half* src =
            (arr ? g_ql : g_qh) + (rbase + (size_t)qb * 128 + r) * CC + coff + c * 8;
        uint32_t dst = sbase + arr * QREG + r * RSA + c * 16;
        CP_ASYNC16(dst, src);
    }

    auto load_stage = [&](int jb, int s) {
        const uint32_t dstb = sbase + SBUF + s * SSZ;
#pragma unroll
        for (int i = 0; i < 8; i++) {
            int idx = tid + i * 256;          // 0..2047
            int sub = idx >> 9;               // 0:KH 1:KL 2:VH 3:VL
            int rem = idx & 511;
            int r = rem >> 3, c = rem & 7;
            const __half* base;
            if (sub == 0)      base = g_kh;
            else if (sub == 1) base = g_kl;
            else if (sub == 2) base = g_vh;
            else               base = g_vl;
            const __half* src = base + (rbase + (size_t)jb * 64 + r) * CC + coff + c * 8;
            uint32_t dst = dstb + sub * 9216 + r * RSA + c * 16;
            CP_ASYNC16(dst, src);
        }
    };

    const int jb_end = 2 * qb + 1;
    load_stage(0, 0);
    CP_COMMIT();            // group: Q + stage0

    float oacc[8][4];
#pragma unroll
    for (int n = 0; n < 8; n++)
#pragma unroll
        for (int v = 0; v < 4; v++) oacc[n][v] = 0.0f;
    float m0 = -1e30f, m1 = -1e30f, l0s = 0.0f, l1s = 0.0f;
    uint32_t qh[4][4], ql[4][4];

    const int qrow0 = qb * 128 + w * 16 + g;

    for (int jb = 0; jb <= jb_end; jb++) {
        const int buf = jb & 1;
        if (jb + 1 <= jb_end) load_stage(jb + 1, buf ^ 1);
        CP_COMMIT();
        CP_WAIT1();
        __syncthreads();

        if (jb == 0) {   // Q fragments (once)
#pragma unroll
            for (int kt = 0; kt < 4; kt++) {
                uint32_t addr = sbase + (w * 16 + (lane & 15)) * RSA
                              + (lane >> 4) * 16 + kt * 32;
                ldsm_x4(qh[kt], addr);
                ldsm_x4(ql[kt], addr + QREG);
            }
        }

        const uint32_t KhB = sbase + SBUF + buf * SSZ;
        const uint32_t KlB = KhB + 9216;
        const uint32_t VhB = KhB + 18432;
        const uint32_t VlB = KhB + 27648;

        const bool active = (jb * 64 <= qb * 128 + w * 16 + 15);
        if (active) {
            // ---- S = Q K^T (3 products, product-major per kt) ----
            float sacc[8][4];
#pragma unroll
            for (int n = 0; n < 8; n++)
#pragma unroll
                for (int v = 0; v < 4; v++) sacc[n][v] = 0.0f;
#pragma unroll
            for (int kt = 0; kt < 4; kt++) {
                uint32_t bh[8][2], bl[8][2];
#pragma unroll
                for (int n = 0; n < 8; n++) {
                    uint32_t baddr = (n * 8 + (lane & 7)) * RSA + kt * 32
                                   + ((lane >> 3) & 1) * 16;
                    ldsm_x2(bh[n], KhB + baddr);
                    ldsm_x2(bl[n], KlB + baddr);
                }
#pragma unroll
                for (int n = 0; n < 8; n++) mma_f16(sacc[n], qh[kt], bh[n]);
#pragma unroll
                for (int n = 0; n < 8; n++) mma_f16(sacc[n], ql[kt], bh[n]);
#pragma unroll
                for (int n = 0; n < 8; n++) mma_f16(sacc[n], qh[kt], bl[n]);
            }

            // ---- causal mask ----
            if (jb * 64 + 63 > qrow0) {
#pragma unroll
                for (int n = 0; n < 8; n++) {
                    int colb = jb * 64 + n * 8 + t * 2;
                    if (colb     > qrow0)     sacc[n][0] = -1e30f;
                    if (colb + 1 > qrow0)     sacc[n][1] = -1e30f;
                    if (colb     > qrow0 + 8) sacc[n][2] = -1e30f;
                    if (colb + 1 > qrow0 + 8) sacc[n][3] = -1e30f;
                }
            }

            // ---- online softmax ----
            float rmax0 = -1e30f, rmax1 = -1e30f;
#pragma unroll
            for (int n = 0; n < 8; n++) {
                rmax0 = fmaxf(rmax0, fmaxf(sacc[n][0], sacc[n][1]));
                rmax1 = fmaxf(rmax1, fmaxf(sacc[n][2], sacc[n][3]));
            }
            rmax0 = fmaxf(rmax0, __shfl_xor_sync(0xffffffffu, rmax0, 1));
            rmax0 = fmaxf(rmax0, __shfl_xor_sync(0xffffffffu, rmax0, 2));
            rmax1 = fmaxf(rmax1, __shfl_xor_sync(0xffffffffu, rmax1, 1));
            rmax1 = fmaxf(rmax1, __shfl_xor_sync(0xffffffffu, rmax1, 2));

            const float mn0 = fmaxf(m0, rmax0), mn1 = fmaxf(m1, rmax1);
            const float c0 = __expf(m0 - mn0), c1 = __expf(m1 - mn1);
            float rs0 = 0.0f, rs1 = 0.0f;
#pragma unroll
            for (int n = 0; n < 8; n++) {
                sacc[n][0] = __expf(sacc[n][0] - mn0);
                sacc[n][1] = __expf(sacc[n][1] - mn0);
                sacc[n][2] = __expf(sacc[n][2] - mn1);
                sacc[n][3] = __expf(sacc[n][3] - mn1);
                rs0 += sacc[n][0] + sacc[n][1];
                rs1 += sacc[n][2] + sacc[n][3];
            }
            rs0 += __shfl_xor_sync(0xffffffffu, rs0, 1);
            rs0 += __shfl_xor_sync(0xffffffffu, rs0, 2);
            rs1 += __shfl_xor_sync(0xffffffffu, rs1, 1);
            rs1 += __shfl_xor_sync(0xffffffffu, rs1, 2);
            l0s = l0s * c0 + rs0; l1s = l1s * c1 + rs1;
            m0 = mn0; m1 = mn1;
#pragma unroll
            for (int n = 0; n < 8; n++) {
                oacc[n][0] *= c0; oacc[n][1] *= c0;
                oacc[n][2] *= c1; oacc[n][3] *= c1;
            }

            // ---- O += P V (3 products, product-major per kt); V via trans-ldsm ----
#pragma unroll
            for (int kt = 0; kt < 4; kt++) {
                uint32_t pah[4], pal[4];
                split2(sacc[2*kt][0],   sacc[2*kt][1],   pah[0], pal[0]);
                split2(sacc[2*kt][2],   sacc[2*kt][3],   pah[1], pal[1]);
                split2(sacc[2*kt+1][0], sacc[2*kt+1][1], pah[2], pal[2]);
                split2(sacc[2*kt+1][2], sacc[2*kt+1][3], pah[3], pal[3]);
                const uint32_t vrow = (kt * 16 + (lane & 15)) * RSA;
                uint32_t bvh[8][2], bvl[8][2];
#pragma unroll
                for (int n = 0; n < 8; n++) {
                    uint32_t baddr = vrow + n * 16;
                    ldsm_x2_trans(bvh[n], VhB + baddr);
                    ldsm_x2_trans(bvl[n], VlB + baddr);
                }
#pragma unroll
                for (int n = 0; n < 8; n++) mma_f16(oacc[n], pah, bvh[n]);
#pragma unroll
                for (int n = 0; n < 8; n++) mma_f16(oacc[n], pal, bvh[n]);
#pragma unroll
                for (int n = 0; n < 8; n++) mma_f16(oacc[n], pah, bvl[n]);
            }
        }
        __syncthreads();   // buffer consumed before next prefetch overwrites
    }

    // ---- epilogue: normalize, split, store fp16 hi/lo ----
    const float inv0 = 1.0f / l0s, inv1 = 1.0f / l1s;
    const size_t r0 = rbase + (size_t)qb * 128 + w * 16 + g;
#pragma unroll
    for (int n = 0; n < 8; n++) {
        int col = coff + n * 8 + t * 2;
        uint32_t h0, l0, h1, l1;
        split2(oacc[n][0] * inv0, oacc[n][1] * inv0, h0, l0);
        split2(oacc[n][2] * inv1, oacc[n][3] * inv1, h1, l1);
        *(uint32_t*)&g_ah[r0 * CC + col]       = h0;
        *(uint32_t*)&g_al[r0 * CC + col]       = l0;
        *(uint32_t*)&g_ah[(r0 + 8) * CC + col] = h1;
        *(uint32_t*)&g_al[(r0 + 8) * CC + col] = l1;
    }
}

// ---------------------------------------------------------------------------
extern "C" void kernel_launch(void* const* d_in, const int* in_sizes, int n_in,
                              void* d_out, int out_size)
{
    const float* x    = (const float*)d_in[0];
    const float* Wqkv = (const float*)d_in[1];
    const float* Wo   = (const float*)d_in[2];
    float* out        = (float*)d_out;

    __half *xh, *xl, *wqh, *wql, *woh, *wol, *ah, *al;
    cudaGetSymbolAddress((void**)&xh, g_xh);   cudaGetSymbolAddress((void**)&xl, g_xl);
    cudaGetSymbolAddress((void**)&wqh, g_wqh); cudaGetSymbolAddress((void**)&wql, g_wql);
    cudaGetSymbolAddress((void**)&woh, g_woh); cudaGetSymbolAddress((void**)&wol, g_wol);
    cudaGetSymbolAddress((void**)&ah, g_ah);   cudaGetSymbolAddress((void**)&al, g_al);

    cudaFuncSetAttribute(gemm_f16x3_kernel<0>,
                         cudaFuncAttributeMaxDynamicSharedMemorySize, GEMM_SMEM);
    cudaFuncSetAttribute(gemm_f16x3_kernel<1>,
                         cudaFuncAttributeMaxDynamicSharedMemorySize, GEMM_SMEM);
    cudaFuncSetAttribute(attn_mma_kernel,
                         cudaFuncAttributeMaxDynamicSharedMemorySize, ATT_SMEM);

    // merged split-fp16 conversion (x | Wqkv | Wo)
    cvt_split_all_kernel<<<(N4_ALL + 255)/256, 256>>>(
        (const float4*)x, (const float4*)Wqkv, (const float4*)Wo);

    // 1) qkv projection; epilogue emits pre-split q(scaled)/k/v, natural layout
    {
        dim3 grid(C3 / 64, BT / 128);
        gemm_f16x3_kernel<1><<<grid, 256, GEMM_SMEM>>>(
            xh, xl, wqh, wql, (float*)nullptr, BT, C3, CC);
    }
    // 2) causal flash attention (HMMA split-fp16)
    {
        dim3 grid(TT / 128, BB * HH);
        attn_mma_kernel<<<grid, 256, ATT_SMEM>>>();
    }
    // 3) out = att @ Wo^T (fp32 result)
    {
        dim3 grid(CC / 64, BT / 128);
        gemm_f16x3_kernel<0><<<grid, 256, GEMM_SMEM>>>(
            ah, al, woh, wol, out, BT, CC, CC);
    }
}

// round 11
// speedup vs baseline: 1.3858x; 1.3382x over previous
#include <cuda_runtime.h>
#include <cuda_fp16.h>
#include <cstdint>
#include <cstddef>

// Problem constants
#define BB 4
#define TT 2048
#define CC 1024
#define HH 16
#define DK 64
#define BT (BB*TT)        // 8192
#define C3 (3*CC)         // 3072

// ---------------------------------------------------------------------------
// Scratch (allocation-free rule: device globals)
// ---------------------------------------------------------------------------
__device__ __half g_xh[(size_t)BT * CC],  g_xl[(size_t)BT * CC];
__device__ __half g_wqh[(size_t)C3 * CC];          // hi only
__device__ __half g_woh[(size_t)CC * CC];          // hi only
// attention operands (GEMM1 epilogue): q split+scaled, k/v hi only
__device__ __half g_qh[(size_t)BT * CC],  g_ql[(size_t)BT * CC];
__device__ __half g_kh[(size_t)BT * CC];
__device__ __half g_vh[(size_t)BT * CC];
// attention output, split (A-operand of GEMM2)
__device__ __half g_ah[(size_t)BT * CC],  g_al[(size_t)BT * CC];

extern __shared__ char dynsm[];

__device__ __forceinline__ uint32_t smem_to_u32(const void* p) {
    uint32_t a;
    asm("{ .reg .u64 t; cvta.to.shared.u64 t, %1; cvt.u32.u64 %0, t; }"
        : "=r"(a) : "l"(p));
    return a;
}
__device__ __forceinline__ void mma_f16(float* c, const uint32_t* a, const uint32_t* b) {
    asm volatile("mma.sync.aligned.m16n8k16.row.col.f32.f16.f16.f32 "
        "{%0,%1,%2,%3}, {%4,%5,%6,%7}, {%8,%9}, {%0,%1,%2,%3};"
        : "+f"(c[0]), "+f"(c[1]), "+f"(c[2]), "+f"(c[3])
        : "r"(a[0]), "r"(a[1]), "r"(a[2]), "r"(a[3]), "r"(b[0]), "r"(b[1]));
}
__device__ __forceinline__ void ldsm_x4(uint32_t* r, uint32_t addr) {
    asm volatile("ldmatrix.sync.aligned.m8n8.x4.shared.b16 {%0,%1,%2,%3}, [%4];"
        : "=r"(r[0]), "=r"(r[1]), "=r"(r[2]), "=r"(r[3]) : "r"(addr));
}
__device__ __forceinline__ void ldsm_x2(uint32_t* r, uint32_t addr) {
    asm volatile("ldmatrix.sync.aligned.m8n8.x2.shared.b16 {%0,%1}, [%2];"
        : "=r"(r[0]), "=r"(r[1]) : "r"(addr));
}
__device__ __forceinline__ void ldsm_x2_trans(uint32_t* r, uint32_t addr) {
    asm volatile("ldmatrix.sync.aligned.m8n8.x2.trans.shared.b16 {%0,%1}, [%2];"
        : "=r"(r[0]), "=r"(r[1]) : "r"(addr));
}
#define CP_ASYNC16(dst, src) \
    asm volatile("cp.async.cg.shared.global [%0], [%1], 16;" :: "r"(dst), "l"(src))
#define CP_COMMIT()  asm volatile("cp.async.commit_group;" ::: "memory")
#define CP_WAIT1()   asm volatile("cp.async.wait_group 1;" ::: "memory")

__device__ __forceinline__ void split2(float a, float b, uint32_t& h, uint32_t& l) {
    __half ha = __float2half_rn(a), hb = __float2half_rn(b);
    __half la = __float2half_rn(a - __half2float(ha));
    __half lb = __float2half_rn(b - __half2float(hb));
    __half2 hp = __halves2half2(ha, hb);
    __half2 lp = __halves2half2(la, lb);
    h = *(uint32_t*)&hp; l = *(uint32_t*)&lp;
}
__device__ __forceinline__ uint32_t pack_hi(float a, float b) {
    __half2 hp = __halves2half2(__float2half_rn(a), __float2half_rn(b));
    return *(uint32_t*)&hp;
}

// ---------------------------------------------------------------------------
// Merged conversion: x -> split (xh,xl); Wqkv, Wo -> hi only
// ---------------------------------------------------------------------------
#define N4_X   (BT * CC / 4)
#define N4_WQ  (C3 * CC / 4)
#define N4_WO  (CC * CC / 4)
#define N4_ALL (N4_X + N4_WQ + N4_WO)

__global__ void cvt_all_kernel(const float4* __restrict__ x,
                               const float4* __restrict__ wq,
                               const float4* __restrict__ wo)
{
    int i = blockIdx.x * blockDim.x + threadIdx.x;
    if (i >= N4_ALL) return;
    if (i < N4_X) {
        float4 v = x[i];
        uint32_t h0, h1, l0, l1;
        split2(v.x, v.y, h0, l0);
        split2(v.z, v.w, h1, l1);
        ((uint32_t*)g_xh)[2*i] = h0; ((uint32_t*)g_xh)[2*i+1] = h1;
        ((uint32_t*)g_xl)[2*i] = l0; ((uint32_t*)g_xl)[2*i+1] = l1;
    } else if (i < N4_X + N4_WQ) {
        int j = i - N4_X;
        float4 v = wq[j];
        ((uint32_t*)g_wqh)[2*j]   = pack_hi(v.x, v.y);
        ((uint32_t*)g_wqh)[2*j+1] = pack_hi(v.z, v.w);
    } else {
        int j = i - N4_X - N4_WQ;
        float4 v = wo[j];
        ((uint32_t*)g_woh)[2*j]   = pack_hi(v.x, v.y);
        ((uint32_t*)g_woh)[2*j+1] = pack_hi(v.z, v.w);
    }
}

// ---------------------------------------------------------------------------
// HMMA 2-product GEMM: C = (Ah+Al) @ Bh^T. CTA tile 128x64, 8 warps (32x32),
// 3-stage cp.async, 2 CTAs/SM.
// MODE 0: C fp32.  MODE 1: qkv epilogue (q split+scaled, k/v hi only).
// ---------------------------------------------------------------------------
#define RS_B     80
#define A_TILE_B (128*RS_B)         // 10240
#define B_TILE_B (64*RS_B)          // 5120
#define STAGE_B  (2*A_TILE_B + B_TILE_B)     // 25600
#define STAGES   3
#define GEMM_SMEM (STAGES*STAGE_B)  // 76800 (x2 CTAs = 153600)

template<int MODE>
__global__ __launch_bounds__(256, 2) void gemm_f16x2_kernel(
    const __half* __restrict__ Ah, const __half* __restrict__ Al,
    const __half* __restrict__ Bh,
    float* __restrict__ C, int M, int N, int K)
{
    const int tid = threadIdx.x, lane = tid & 31, wid = tid >> 5;
    const int bm = blockIdx.y * 128, bn = blockIdx.x * 64;
    const int wr = wid >> 1, wc = wid & 1;     // 4x2 warp grid, 32x32 tiles
    const uint32_t sbase = smem_to_u32(dynsm);
    const int NC = K / 32;

    float acc[2][4][4];
#pragma unroll
    for (int i = 0; i < 2; i++)
#pragma unroll
        for (int j = 0; j < 4; j++)
#pragma unroll
            for (int v = 0; v < 4; v++) acc[i][j][v] = 0.0f;

    // 1280 16B-chunks per stage: Ah 512, Al 512, Bh 256. 5 per thread.
    auto load_stage = [&](int st, int buf) {
        const int kk = st * 32;
        const uint32_t dstb = sbase + buf * STAGE_B;
#pragma unroll
        for (int i = 0; i < 5; i++) {
            int c = tid + i * 256;                 // 0..1279
            const __half* src;
            uint32_t dst;
            if (c < 1024) {
                int arr = c >> 9, rc = c & 511;
                int row = rc >> 2, kc = rc & 3;
                src = (arr ? Al : Ah) + (size_t)(bm + row) * K + kk + kc * 8;
                dst = dstb + arr * A_TILE_B + row * RS_B + kc * 16;
            } else {
                int cb = c - 1024;
                int row = cb >> 2, kc = cb & 3;
                src = Bh + (size_t)(bn + row) * K + kk + kc * 8;
                dst = dstb + 2 * A_TILE_B + row * RS_B + kc * 16;
            }
            CP_ASYNC16(dst, src);
        }
    };

    const uint32_t a_off0 = (wr * 32 + (lane & 15)) * RS_B + (lane >> 4) * 16;
    const uint32_t b_off0 = (wc * 32 + (lane & 7)) * RS_B + ((lane >> 3) & 1) * 16;

    load_stage(0, 0); CP_COMMIT();
    load_stage(1, 1); CP_COMMIT();

    for (int it = 0; it < NC; it++) {
        CP_WAIT1();
        __syncthreads();
        const int nxt = it + (STAGES - 1);
        if (nxt < NC) load_stage(nxt, nxt % STAGES);
        CP_COMMIT();

        const uint32_t tb = sbase + (it % STAGES) * STAGE_B;
#pragma unroll
        for (int ks = 0; ks < 2; ks++) {
            uint32_t ah[2][4], al[2][4], bh[4][2];
#pragma unroll
            for (int mt = 0; mt < 2; mt++) {
                uint32_t aaddr = tb + a_off0 + mt * (16 * RS_B) + ks * 32;
                ldsm_x4(ah[mt], aaddr);
                ldsm_x4(al[mt], aaddr + A_TILE_B);
            }
#pragma unroll
            for (int nt = 0; nt < 4; nt++) {
                uint32_t baddr = tb + 2 * A_TILE_B + b_off0 + nt * (8 * RS_B) + ks * 32;
                ldsm_x2(bh[nt], baddr);
            }
            // product-major: same-acc MMAs spaced by 8
#pragma unroll
            for (int mt = 0; mt < 2; mt++)
#pragma unroll
                for (int nt = 0; nt < 4; nt++) mma_f16(acc[mt][nt], ah[mt], bh[nt]);
#pragma unroll
            for (int mt = 0; mt < 2; mt++)
#pragma unroll
                for (int nt = 0; nt < 4; nt++) mma_f16(acc[mt][nt], al[mt], bh[nt]);
        }
    }

    // epilogue
    const int g = lane >> 2, t = lane & 3;
#pragma unroll
    for (int mt = 0; mt < 2; mt++) {
#pragma unroll
        for (int nt = 0; nt < 4; nt++) {
            int row = bm + wr * 32 + mt * 16 + g;
            int col = bn + wc * 32 + nt * 8 + t * 2;
            if (MODE == 0) {
                *(float2*)&C[(size_t)row * N + col] =
                    make_float2(acc[mt][nt][0], acc[mt][nt][1]);
                *(float2*)&C[(size_t)(row + 8) * N + col] =
                    make_float2(acc[mt][nt][2], acc[mt][nt][3]);
            } else {
                if (bn < CC) {                     // q: scale, split
                    uint32_t h0, l0, h1, l1;
                    split2(acc[mt][nt][0]*0.125f, acc[mt][nt][1]*0.125f, h0, l0);
                    split2(acc[mt][nt][2]*0.125f, acc[mt][nt][3]*0.125f, h1, l1);
                    *(uint32_t*)&g_qh[(size_t)row * CC + col]       = h0;
                    *(uint32_t*)&g_ql[(size_t)row * CC + col]       = l0;
                    *(uint32_t*)&g_qh[(size_t)(row + 8) * CC + col] = h1;
                    *(uint32_t*)&g_ql[(size_t)(row + 8) * CC + col] = l1;
                } else if (bn < 2 * CC) {          // k: hi only
                    int cc = col - CC;
                    *(uint32_t*)&g_kh[(size_t)row * CC + cc] =
                        pack_hi(acc[mt][nt][0], acc[mt][nt][1]);
                    *(uint32_t*)&g_kh[(size_t)(row + 8) * CC + cc] =
                        pack_hi(acc[mt][nt][2], acc[mt][nt][3]);
                } else {                            // v: hi only
                    int cc = col - 2 * CC;
                    *(uint32_t*)&g_vh[(size_t)row * CC + cc] =
                        pack_hi(acc[mt][nt][0], acc[mt][nt][1]);
                    *(uint32_t*)&g_vh[(size_t)(row + 8) * CC + cc] =
                        pack_hi(acc[mt][nt][2], acc[mt][nt][3]);
                }
            }
        }
    }
}

// ---------------------------------------------------------------------------
// HMMA 2-product flash attention, causal. Q split / K hi; P split / V hi.
// ---------------------------------------------------------------------------
#define RSA   144
#define QREG  18432                 // 128*144
#define SBUF  (2*QREG)              // 36864
#define SSZ   18432                 // KH + VH @ 9216 each
#define ATT_SMEM (SBUF + 2*SSZ)     // 73728

__global__ __launch_bounds__(256, 1) void attn_mma_kernel()
{
    const uint32_t sbase = smem_to_u32(dynsm);
    const int tid = threadIdx.x, lane = tid & 31, w = tid >> 5;
    const int qb = blockIdx.x;
    const int b  = blockIdx.y >> 4;
    const int h  = blockIdx.y & 15;
    const size_t rbase = (size_t)b * TT;
    const int coff = h * DK;
    const int g = lane >> 2, t = lane & 3;

    // ---- stage Q (hi+lo) via cp.async ----
#pragma unroll
    for (int i = 0; i < 8; i++) {
        int idx = tid + i * 256;              // 0..2047
        int arr = idx >> 10;                  // 0: qh, 1: ql
        int rem = idx & 1023;
        int r = rem >> 3, c = rem & 7;
        const __half* src =
            (arr ? g_ql : g_qh) + (rbase + (size_t)qb * 128 + r) * CC + coff + c * 8;
        uint32_t dst = sbase + arr * QREG + r * RSA + c * 16;
        CP_ASYNC16(dst, src);
    }

    auto load_stage = [&](int jb, int s) {
        const uint32_t dstb = sbase + SBUF + s * SSZ;
#pragma unroll
        for (int i = 0; i < 4; i++) {
            int idx = tid + i * 256;          // 0..1023
            int sub = idx >> 9;               // 0:KH 1:VH
            int rem = idx & 511;
            int r = rem >> 3, c = rem & 7;
            const __half* base = sub ? g_vh : g_kh;
            const __half* src = base + (rbase + (size_t)jb * 64 + r) * CC + coff + c * 8;
            uint32_t dst = dstb + sub * 9216 + r * RSA + c * 16;
            CP_ASYNC16(dst, src);
        }
    };

    const int jb_end = 2 * qb + 1;
    load_stage(0, 0);
    CP_COMMIT();            // group: Q + stage0

    float oacc[8][4];
#pragma unroll
    for (int n = 0; n < 8; n++)
#pragma unroll
        for (int v = 0; v < 4; v++) oacc[n][v] = 0.0f;
    float m0 = -1e30f, m1 = -1e30f, l0s = 0.0f, l1s = 0.0f;
    uint32_t qh[4][4], ql[4][4];

    const int qrow0 = qb * 128 + w * 16 + g;

    for (int jb = 0; jb <= jb_end; jb++) {
        const int buf = jb & 1;
        if (jb + 1 <= jb_end) load_stage(jb + 1, buf ^ 1);
        CP_COMMIT();
        CP_WAIT1();
        __syncthreads();

        if (jb == 0) {   // Q fragments (once)
#pragma unroll
            for (int kt = 0; kt < 4; kt++) {
                uint32_t addr = sbase + (w * 16 + (lane & 15)) * RSA
                              + (lane >> 4) * 16 + kt * 32;
                ldsm_x4(qh[kt], addr);
                ldsm_x4(ql[kt], addr + QREG);
            }
        }

        const uint32_t KhB = sbase + SBUF + buf * SSZ;
        const uint32_t VhB = KhB + 9216;

        const bool active = (jb * 64 <= qb * 128 + w * 16 + 15);
        if (active) {
            // ---- S = Q K^T (2 products) ----
            float sacc[8][4];
#pragma unroll
            for (int n = 0; n < 8; n++)
#pragma unroll
                for (int v = 0; v < 4; v++) sacc[n][v] = 0.0f;
#pragma unroll
            for (int kt = 0; kt < 4; kt++) {
                uint32_t bh[8][2];
#pragma unroll
                for (int n = 0; n < 8; n++) {
                    uint32_t baddr = (n * 8 + (lane & 7)) * RSA + kt * 32
                                   + ((lane >> 3) & 1) * 16;
                    ldsm_x2(bh[n], KhB + baddr);
                }
#pragma unroll
                for (int n = 0; n < 8; n++) mma_f16(sacc[n], qh[kt], bh[n]);
#pragma unroll
                for (int n = 0; n < 8; n++) mma_f16(sacc[n], ql[kt], bh[n]);
            }

            // ---- causal mask ----
            if (jb * 64 + 63 > qrow0) {
#pragma unroll
                for (int n = 0; n < 8; n++) {
                    int colb = jb * 64 + n * 8 + t * 2;
                    if (colb     > qrow0)     sacc[n][0] = -1e30f;
                    if (colb + 1 > qrow0)     sacc[n][1] = -1e30f;
                    if (colb     > qrow0 + 8) sacc[n][2] = -1e30f;
                    if (colb + 1 > qrow0 + 8) sacc[n][3] = -1e30f;
                }
            }

            // ---- online softmax ----
            float rmax0 = -1e30f, rmax1 = -1e30f;
#pragma unroll
            for (int n = 0; n < 8; n++) {
                rmax0 = fmaxf(rmax0, fmaxf(sacc[n][0], sacc[n][1]));
                rmax1 = fmaxf(rmax1, fmaxf(sacc[n][2], sacc[n][3]));
            }
            rmax0 = fmaxf(rmax0, __shfl_xor_sync(0xffffffffu, rmax0, 1));
            rmax0 = fmaxf(rmax0, __shfl_xor_sync(0xffffffffu, rmax0, 2));
            rmax1 = fmaxf(rmax1, __shfl_xor_sync(0xffffffffu, rmax1, 1));
            rmax1 = fmaxf(rmax1, __shfl_xor_sync(0xffffffffu, rmax1, 2));

            const float mn0 = fmaxf(m0, rmax0), mn1 = fmaxf(m1, rmax1);
            const float c0 = __expf(m0 - mn0), c1 = __expf(m1 - mn1);
            float rs0 = 0.0f, rs1 = 0.0f;
#pragma unroll
            for (int n = 0; n < 8; n++) {
                sacc[n][0] = __expf(sacc[n][0] - mn0);
                sacc[n][1] = __expf(sacc[n][1] - mn0);
                sacc[n][2] = __expf(sacc[n][2] - mn1);
                sacc[n][3] = __expf(sacc[n][3] - mn1);
                rs0 += sacc[n][0] + sacc[n][1];
                rs1 += sacc[n][2] + sacc[n][3];
            }
            rs0 += __shfl_xor_sync(0xffffffffu, rs0, 1);
            rs0 += __shfl_xor_sync(0xffffffffu, rs0, 2);
            rs1 += __shfl_xor_sync(0xffffffffu, rs1, 1);
            rs1 += __shfl_xor_sync(0xffffffffu, rs1, 2);
            l0s = l0s * c0 + rs0; l1s = l1s * c1 + rs1;
            m0 = mn0; m1 = mn1;
#pragma unroll
            for (int n = 0; n < 8; n++) {
                oacc[n][0] *= c0; oacc[n][1] *= c0;
                oacc[n][2] *= c1; oacc[n][3] *= c1;
            }

            // ---- O += P V (2 products); V via trans-ldsm ----
#pragma unroll
            for (int kt = 0; kt < 4; kt++) {
                uint32_t pah[4], pal[4];
                split2(sacc[2*kt][0],   sacc[2*kt][1],   pah[0], pal[0]);
                split2(sacc[2*kt][2],   sacc[2*kt][3],   pah[1], pal[1]);
                split2(sacc[2*kt+1][0], sacc[2*kt+1][1], pah[2], pal[2]);
                split2(sacc[2*kt+1][2], sacc[2*kt+1][3], pah[3], pal[3]);
                const uint32_t vrow = (kt * 16 + (lane & 15)) * RSA;
                uint32_t bvh[8][2];
#pragma unroll
                for (int n = 0; n < 8; n++) {
                    ldsm_x2_trans(bvh[n], VhB + vrow + n * 16);
                }
#pragma unroll
                for (int n = 0; n < 8; n++) mma_f16(oacc[n], pah, bvh[n]);
#pragma unroll
                for (int n = 0; n < 8; n++) mma_f16(oacc[n], pal, bvh[n]);
            }
        }
        __syncthreads();   // buffer consumed before next prefetch overwrites
    }

    // ---- epilogue: normalize, split, store fp16 hi/lo ----
    const float inv0 = 1.0f / l0s, inv1 = 1.0f / l1s;
    const size_t r0 = rbase + (size_t)qb * 128 + w * 16 + g;
#pragma unroll
    for (int n = 0; n < 8; n++) {
        int col = coff + n * 8 + t * 2;
        uint32_t h0, l0, h1, l1;
        split2(oacc[n][0] * inv0, oacc[n][1] * inv0, h0, l0);
        split2(oacc[n][2] * inv1, oacc[n][3] * inv1, h1, l1);
        *(uint32_t*)&g_ah[r0 * CC + col]       = h0;
        *(uint32_t*)&g_al[r0 * CC + col]       = l0;
        *(uint32_t*)&g_ah[(r0 + 8) * CC + col] = h1;
        *(uint32_t*)&g_al[(r0 + 8) * CC + col] = l1;
    }
}

// ---------------------------------------------------------------------------
extern "C" void kernel_launch(void* const* d_in, const int* in_sizes, int n_in,
                              void* d_out, int out_size)
{
    const float* x    = (const float*)d_in[0];
    const float* Wqkv = (const float*)d_in[1];
    const float* Wo   = (const float*)d_in[2];
    float* out        = (float*)d_out;

    __half *xh, *xl, *wqh, *woh, *ah, *al;
    cudaGetSymbolAddress((void**)&xh, g_xh);   cudaGetSymbolAddress((void**)&xl, g_xl);
    cudaGetSymbolAddress((void**)&wqh, g_wqh); cudaGetSymbolAddress((void**)&woh, g_woh);
    cudaGetSymbolAddress((void**)&ah, g_ah);   cudaGetSymbolAddress((void**)&al, g_al);

    cudaFuncSetAttribute(gemm_f16x2_kernel<0>,
                         cudaFuncAttributeMaxDynamicSharedMemorySize, GEMM_SMEM);
    cudaFuncSetAttribute(gemm_f16x2_kernel<1>,
                         cudaFuncAttributeMaxDynamicSharedMemorySize, GEMM_SMEM);
    cudaFuncSetAttribute(attn_mma_kernel,
                         cudaFuncAttributeMaxDynamicSharedMemorySize, ATT_SMEM);

    // merged conversion (x split; Wqkv/Wo hi-only)
    cvt_all_kernel<<<(N4_ALL + 255)/256, 256>>>(
        (const float4*)x, (const float4*)Wqkv, (const float4*)Wo);

    // 1) qkv projection (2-product); epilogue: q split+scaled, k/v hi only
    {
        dim3 grid(C3 / 64, BT / 128);
        gemm_f16x2_kernel<1><<<grid, 256, GEMM_SMEM>>>(
            xh, xl, wqh, (float*)nullptr, BT, C3, CC);
    }
    // 2) causal flash attention (2-product)
    {
        dim3 grid(TT / 128, BB * HH);
        attn_mma_kernel<<<grid, 256, ATT_SMEM>>>();
    }
    // 3) out = att @ Wo^T (2-product, fp32 result)
    {
        dim3 grid(CC / 64, BT / 128);
        gemm_f16x2_kernel<0><<<grid, 256, GEMM_SMEM>>>(
            ah, al, woh, out, BT, CC, CC);
    }
}

// round 12
// speedup vs baseline: 1.9328x; 1.3947x over previous
#include <cuda_runtime.h>
#include <cuda_fp16.h>
#include <cstdint>
#include <cstddef>

// Problem constants
#define BB 4
#define TT 2048
#define CC 1024
#define HH 16
#define DK 64
#define BT (BB*TT)        // 8192
#define C3 (3*CC)         // 3072

// ---------------------------------------------------------------------------
// Scratch (allocation-free rule: device globals)
// ---------------------------------------------------------------------------
__device__ __half g_xh[(size_t)BT * CC];           // x hi
__device__ __half g_wqh[(size_t)C3 * CC];          // Wqkv hi
__device__ __half g_woh[(size_t)CC * CC];          // Wo hi
// attention operands (GEMM1 epilogue): q split+scaled, k/v hi only
__device__ __half g_qh[(size_t)BT * CC],  g_ql[(size_t)BT * CC];
__device__ __half g_kh[(size_t)BT * CC];
__device__ __half g_vh[(size_t)BT * CC];
// attention output, hi only (A-operand of GEMM2)
__device__ __half g_ah[(size_t)BT * CC];

extern __shared__ char dynsm[];

__device__ __forceinline__ uint32_t smem_to_u32(const void* p) {
    uint32_t a;
    asm("{ .reg .u64 t; cvta.to.shared.u64 t, %1; cvt.u32.u64 %0, t; }"
        : "=r"(a) : "l"(p));
    return a;
}
__device__ __forceinline__ void mma_f16(float* c, const uint32_t* a, const uint32_t* b) {
    asm volatile("mma.sync.aligned.m16n8k16.row.col.f32.f16.f16.f32 "
        "{%0,%1,%2,%3}, {%4,%5,%6,%7}, {%8,%9}, {%0,%1,%2,%3};"
        : "+f"(c[0]), "+f"(c[1]), "+f"(c[2]), "+f"(c[3])
        : "r"(a[0]), "r"(a[1]), "r"(a[2]), "r"(a[3]), "r"(b[0]), "r"(b[1]));
}
__device__ __forceinline__ void ldsm_x4(uint32_t* r, uint32_t addr) {
    asm volatile("ldmatrix.sync.aligned.m8n8.x4.shared.b16 {%0,%1,%2,%3}, [%4];"
        : "=r"(r[0]), "=r"(r[1]), "=r"(r[2]), "=r"(r[3]) : "r"(addr));
}
__device__ __forceinline__ void ldsm_x2(uint32_t* r, uint32_t addr) {
    asm volatile("ldmatrix.sync.aligned.m8n8.x2.shared.b16 {%0,%1}, [%2];"
        : "=r"(r[0]), "=r"(r[1]) : "r"(addr));
}
__device__ __forceinline__ void ldsm_x2_trans(uint32_t* r, uint32_t addr) {
    asm volatile("ldmatrix.sync.aligned.m8n8.x2.trans.shared.b16 {%0,%1}, [%2];"
        : "=r"(r[0]), "=r"(r[1]) : "r"(addr));
}
#define CP_ASYNC16(dst, src) \
    asm volatile("cp.async.cg.shared.global [%0], [%1], 16;" :: "r"(dst), "l"(src))
#define CP_COMMIT()  asm volatile("cp.async.commit_group;" ::: "memory")
#define CP_WAIT1()   asm volatile("cp.async.wait_group 1;" ::: "memory")

__device__ __forceinline__ void split2(float a, float b, uint32_t& h, uint32_t& l) {
    __half ha = __float2half_rn(a), hb = __float2half_rn(b);
    __half la = __float2half_rn(a - __half2float(ha));
    __half lb = __float2half_rn(b - __half2float(hb));
    __half2 hp = __halves2half2(ha, hb);
    __half2 lp = __halves2half2(la, lb);
    h = *(uint32_t*)&hp; l = *(uint32_t*)&lp;
}
__device__ __forceinline__ uint32_t pack_hi(float a, float b) {
    __half2 hp = __halves2half2(__float2half_rn(a), __float2half_rn(b));
    return *(uint32_t*)&hp;
}

// ---------------------------------------------------------------------------
// Merged conversion: x, Wqkv, Wo -> fp16 hi only
// ---------------------------------------------------------------------------
#define N4_X   (BT * CC / 4)
#define N4_WQ  (C3 * CC / 4)
#define N4_WO  (CC * CC / 4)
#define N4_ALL (N4_X + N4_WQ + N4_WO)

__global__ void cvt_all_kernel(const float4* __restrict__ x,
                               const float4* __restrict__ wq,
                               const float4* __restrict__ wo)
{
    int i = blockIdx.x * blockDim.x + threadIdx.x;
    if (i >= N4_ALL) return;
    const float4* src;
    uint32_t* dst;
    int j;
    if (i < N4_X)              { j = i;                src = x;  dst = (uint32_t*)g_xh; }
    else if (i < N4_X + N4_WQ) { j = i - N4_X;         src = wq; dst = (uint32_t*)g_wqh; }
    else                       { j = i - N4_X - N4_WQ; src = wo; dst = (uint32_t*)g_woh; }
    float4 v = src[j];
    dst[2*j]   = pack_hi(v.x, v.y);
    dst[2*j+1] = pack_hi(v.z, v.w);
}

// ---------------------------------------------------------------------------
// HMMA single-product fp16 GEMM: C = Ah @ Bh^T. CTA tile 128x64, 8 warps
// (32x32), 3-stage cp.async, 2 CTAs/SM.
// MODE 0: C fp32.  MODE 1: qkv epilogue (q split+scaled, k/v hi only).
// ---------------------------------------------------------------------------
#define RS_B     80
#define A_TILE_B (128*RS_B)         // 10240
#define B_TILE_B (64*RS_B)          // 5120
#define STAGE_B  (A_TILE_B + B_TILE_B)   // 15360
#define STAGES   3
#define GEMM_SMEM (STAGES*STAGE_B)  // 46080 (x2 CTAs = 92160)

template<int MODE>
__global__ __launch_bounds__(256, 2) void gemm_f16x1_kernel(
    const __half* __restrict__ Ah, const __half* __restrict__ Bh,
    float* __restrict__ C, int M, int N, int K)
{
    const int tid = threadIdx.x, lane = tid & 31, wid = tid >> 5;
    const int bm = blockIdx.y * 128, bn = blockIdx.x * 64;
    const int wr = wid >> 1, wc = wid & 1;     // 4x2 warp grid, 32x32 tiles
    const uint32_t sbase = smem_to_u32(dynsm);
    const int NC = K / 32;

    float acc[2][4][4];
#pragma unroll
    for (int i = 0; i < 2; i++)
#pragma unroll
        for (int j = 0; j < 4; j++)
#pragma unroll
            for (int v = 0; v < 4; v++) acc[i][j][v] = 0.0f;

    // 768 16B-chunks per stage: Ah 512, Bh 256. 3 per thread.
    auto load_stage = [&](int st, int buf) {
        const int kk = st * 32;
        const uint32_t dstb = sbase + buf * STAGE_B;
#pragma unroll
        for (int i = 0; i < 3; i++) {
            int c = tid + i * 256;                 // 0..767
            const __half* src;
            uint32_t dst;
            if (c < 512) {
                int row = c >> 2, kc = c & 3;
                src = Ah + (size_t)(bm + row) * K + kk + kc * 8;
                dst = dstb + row * RS_B + kc * 16;
            } else {
                int cb = c - 512;
                int row = cb >> 2, kc = cb & 3;
                src = Bh + (size_t)(bn + row) * K + kk + kc * 8;
                dst = dstb + A_TILE_B + row * RS_B + kc * 16;
            }
            CP_ASYNC16(dst, src);
        }
    };

    const uint32_t a_off0 = (wr * 32 + (lane & 15)) * RS_B + (lane >> 4) * 16;
    const uint32_t b_off0 = (wc * 32 + (lane & 7)) * RS_B + ((lane >> 3) & 1) * 16;

    load_stage(0, 0); CP_COMMIT();
    load_stage(1, 1); CP_COMMIT();

    for (int it = 0; it < NC; it++) {
        CP_WAIT1();
        __syncthreads();
        const int nxt = it + (STAGES - 1);
        if (nxt < NC) load_stage(nxt, nxt % STAGES);
        CP_COMMIT();

        const uint32_t tb = sbase + (it % STAGES) * STAGE_B;
#pragma unroll
        for (int ks = 0; ks < 2; ks++) {
            uint32_t ah[2][4], bh[4][2];
#pragma unroll
            for (int mt = 0; mt < 2; mt++)
                ldsm_x4(ah[mt], tb + a_off0 + mt * (16 * RS_B) + ks * 32);
#pragma unroll
            for (int nt = 0; nt < 4; nt++)
                ldsm_x2(bh[nt], tb + A_TILE_B + b_off0 + nt * (8 * RS_B) + ks * 32);
#pragma unroll
            for (int mt = 0; mt < 2; mt++)
#pragma unroll
                for (int nt = 0; nt < 4; nt++) mma_f16(acc[mt][nt], ah[mt], bh[nt]);
        }
    }

    // epilogue
    const int g = lane >> 2, t = lane & 3;
#pragma unroll
    for (int mt = 0; mt < 2; mt++) {
#pragma unroll
        for (int nt = 0; nt < 4; nt++) {
            int row = bm + wr * 32 + mt * 16 + g;
            int col = bn + wc * 32 + nt * 8 + t * 2;
            if (MODE == 0) {
                *(float2*)&C[(size_t)row * N + col] =
                    make_float2(acc[mt][nt][0], acc[mt][nt][1]);
                *(float2*)&C[(size_t)(row + 8) * N + col] =
                    make_float2(acc[mt][nt][2], acc[mt][nt][3]);
            } else {
                if (bn < CC) {                     // q: scale, split
                    uint32_t h0, l0, h1, l1;
                    split2(acc[mt][nt][0]*0.125f, acc[mt][nt][1]*0.125f, h0, l0);
                    split2(acc[mt][nt][2]*0.125f, acc[mt][nt][3]*0.125f, h1, l1);
                    *(uint32_t*)&g_qh[(size_t)row * CC + col]       = h0;
                    *(uint32_t*)&g_ql[(size_t)row * CC + col]       = l0;
                    *(uint32_t*)&g_qh[(size_t)(row + 8) * CC + col] = h1;
                    *(uint32_t*)&g_ql[(size_t)(row + 8) * CC + col] = l1;
                } else if (bn < 2 * CC) {          // k: hi only
                    int cc = col - CC;
                    *(uint32_t*)&g_kh[(size_t)row * CC + cc] =
                        pack_hi(acc[mt][nt][0], acc[mt][nt][1]);
                    *(uint32_t*)&g_kh[(size_t)(row + 8) * CC + cc] =
                        pack_hi(acc[mt][nt][2], acc[mt][nt][3]);
                } else {                            // v: hi only
                    int cc = col - 2 * CC;
                    *(uint32_t*)&g_vh[(size_t)row * CC + cc] =
                        pack_hi(acc[mt][nt][0], acc[mt][nt][1]);
                    *(uint32_t*)&g_vh[(size_t)(row + 8) * CC + cc] =
                        pack_hi(acc[mt][nt][2], acc[mt][nt][3]);
                }
            }
        }
    }
}

// ---------------------------------------------------------------------------
// HMMA 2-product flash attention, causal. Q split / K hi; P split / V hi.
// Heavy q-blocks launch first (reversed CTA order) to shorten the tail wave.
// ---------------------------------------------------------------------------
#define RSA   144
#define QREG  18432                 // 128*144
#define SBUF  (2*QREG)              // 36864
#define SSZ   18432                 // KH + VH @ 9216 each
#define ATT_SMEM (SBUF + 2*SSZ)     // 73728

__global__ __launch_bounds__(256, 1) void attn_mma_kernel()
{
    const uint32_t sbase = smem_to_u32(dynsm);
    const int tid = threadIdx.x, lane = tid & 31, w = tid >> 5;
    const int qb = gridDim.x - 1 - blockIdx.x;   // heavy blocks first
    const int b  = blockIdx.y >> 4;
    const int h  = blockIdx.y & 15;
    const size_t rbase = (size_t)b * TT;
    const int coff = h * DK;
    const int g = lane >> 2, t = lane & 3;

    // ---- stage Q (hi+lo) via cp.async ----
#pragma unroll
    for (int i = 0; i < 8; i++) {
        int idx = tid + i * 256;              // 0..2047
        int arr = idx >> 10;                  // 0: qh, 1: ql
        int rem = idx & 1023;
        int r = rem >> 3, c = rem & 7;
        const __half* src =
            (arr ? g_ql : g_qh) + (rbase + (size_t)qb * 128 + r) * CC + coff + c * 8;
        uint32_t dst = sbase + arr * QREG + r * RSA + c * 16;
        CP_ASYNC16(dst, src);
    }

    auto load_stage = [&](int jb, int s) {
        const uint32_t dstb = sbase + SBUF + s * SSZ;
#pragma unroll
        for (int i = 0; i < 4; i++) {
            int idx = tid + i * 256;          // 0..1023
            int sub = idx >> 9;               // 0:KH 1:VH
            int rem = idx & 511;
            int r = rem >> 3, c = rem & 7;
            const __half* base = sub ? g_vh : g_kh;
            const __half* src = base + (rbase + (size_t)jb * 64 + r) * CC + coff + c * 8;
            uint32_t dst = dstb + sub * 9216 + r * RSA + c * 16;
            CP_ASYNC16(dst, src);
        }
    };

    const int jb_end = 2 * qb + 1;
    load_stage(0, 0);
    CP_COMMIT();            // group: Q + stage0

    float oacc[8][4];
#pragma unroll
    for (int n = 0; n < 8; n++)
#pragma unroll
        for (int v = 0; v < 4; v++) oacc[n][v] = 0.0f;
    float m0 = -1e30f, m1 = -1e30f, l0s = 0.0f, l1s = 0.0f;
    uint32_t qh[4][4], ql[4][4];

    const int qrow0 = qb * 128 + w * 16 + g;

    for (int jb = 0; jb <= jb_end; jb++) {
        const int buf = jb & 1;
        if (jb + 1 <= jb_end) load_stage(jb + 1, buf ^ 1);
        CP_COMMIT();
        CP_WAIT1();
        __syncthreads();

        if (jb == 0) {   // Q fragments (once)
#pragma unroll
            for (int kt = 0; kt < 4; kt++) {
                uint32_t addr = sbase + (w * 16 + (lane & 15)) * RSA
                              + (lane >> 4) * 16 + kt * 32;
                ldsm_x4(qh[kt], addr);
                ldsm_x4(ql[kt], addr + QREG);
            }
        }

        const uint32_t KhB = sbase + SBUF + buf * SSZ;
        const uint32_t VhB = KhB + 9216;

        const bool active = (jb * 64 <= qb * 128 + w * 16 + 15);
        if (active) {
            // ---- S = Q K^T (2 products) ----
            float sacc[8][4];
#pragma unroll
            for (int n = 0; n < 8; n++)
#pragma unroll
                for (int v = 0; v < 4; v++) sacc[n][v] = 0.0f;
#pragma unroll
            for (int kt = 0; kt < 4; kt++) {
                uint32_t bh[8][2];
#pragma unroll
                for (int n = 0; n < 8; n++) {
                    uint32_t baddr = (n * 8 + (lane & 7)) * RSA + kt * 32
                                   + ((lane >> 3) & 1) * 16;
                    ldsm_x2(bh[n], KhB + baddr);
                }
#pragma unroll
                for (int n = 0; n < 8; n++) mma_f16(sacc[n], qh[kt], bh[n]);
#pragma unroll
                for (int n = 0; n < 8; n++) mma_f16(sacc[n], ql[kt], bh[n]);
            }

            // ---- causal mask ----
            if (jb * 64 + 63 > qrow0) {
#pragma unroll
                for (int n = 0; n < 8; n++) {
                    int colb = jb * 64 + n * 8 + t * 2;
                    if (colb     > qrow0)     sacc[n][0] = -1e30f;
                    if (colb + 1 > qrow0)     sacc[n][1] = -1e30f;
                    if (colb     > qrow0 + 8) sacc[n][2] = -1e30f;
                    if (colb + 1 > qrow0 + 8) sacc[n][3] = -1e30f;
                }
            }

            // ---- online softmax ----
            float rmax0 = -1e30f, rmax1 = -1e30f;
#pragma unroll
            for (int n = 0; n < 8; n++) {
                rmax0 = fmaxf(rmax0, fmaxf(sacc[n][0], sacc[n][1]));
                rmax1 = fmaxf(rmax1, fmaxf(sacc[n][2], sacc[n][3]));
            }
            rmax0 = fmaxf(rmax0, __shfl_xor_sync(0xffffffffu, rmax0, 1));
            rmax0 = fmaxf(rmax0, __shfl_xor_sync(0xffffffffu, rmax0, 2));
            rmax1 = fmaxf(rmax1, __shfl_xor_sync(0xffffffffu, rmax1, 1));
            rmax1 = fmaxf(rmax1, __shfl_xor_sync(0xffffffffu, rmax1, 2));

            const float mn0 = fmaxf(m0, rmax0), mn1 = fmaxf(m1, rmax1);
            const float c0 = __expf(m0 - mn0), c1 = __expf(m1 - mn1);
            float rs0 = 0.0f, rs1 = 0.0f;
#pragma unroll
            for (int n = 0; n < 8; n++) {
                sacc[n][0] = __expf(sacc[n][0] - mn0);
                sacc[n][1] = __expf(sacc[n][1] - mn0);
                sacc[n][2] = __expf(sacc[n][2] - mn1);
                sacc[n][3] = __expf(sacc[n][3] - mn1);
                rs0 += sacc[n][0] + sacc[n][1];
                rs1 += sacc[n][2] + sacc[n][3];
            }
            rs0 += __shfl_xor_sync(0xffffffffu, rs0, 1);
            rs0 += __shfl_xor_sync(0xffffffffu, rs0, 2);
            rs1 += __shfl_xor_sync(0xffffffffu, rs1, 1);
            rs1 += __shfl_xor_sync(0xffffffffu, rs1, 2);
            l0s = l0s * c0 + rs0; l1s = l1s * c1 + rs1;
            m0 = mn0; m1 = mn1;
#pragma unroll
            for (int n = 0; n < 8; n++) {
                oacc[n][0] *= c0; oacc[n][1] *= c0;
                oacc[n][2] *= c1; oacc[n][3] *= c1;
            }

            // ---- O += P V (2 products); V via trans-ldsm ----
#pragma unroll
            for (int kt = 0; kt < 4; kt++) {
                uint32_t pah[4], pal[4];
                split2(sacc[2*kt][0],   sacc[2*kt][1],   pah[0], pal[0]);
                split2(sacc[2*kt][2],   sacc[2*kt][3],   pah[1], pal[1]);
                split2(sacc[2*kt+1][0], sacc[2*kt+1][1], pah[2], pal[2]);
                split2(sacc[2*kt+1][2], sacc[2*kt+1][3], pah[3], pal[3]);
                const uint32_t vrow = (kt * 16 + (lane & 15)) * RSA;
                uint32_t bvh[8][2];
#pragma unroll
                for (int n = 0; n < 8; n++)
                    ldsm_x2_trans(bvh[n], VhB + vrow + n * 16);
#pragma unroll
                for (int n = 0; n < 8; n++) mma_f16(oacc[n], pah, bvh[n]);
#pragma unroll
                for (int n = 0; n < 8; n++) mma_f16(oacc[n], pal, bvh[n]);
            }
        }
        __syncthreads();   // buffer consumed before next prefetch overwrites
    }

    // ---- epilogue: normalize, store fp16 hi ----
    const float inv0 = 1.0f / l0s, inv1 = 1.0f / l1s;
    const size_t r0 = rbase + (size_t)qb * 128 + w * 16 + g;
#pragma unroll
    for (int n = 0; n < 8; n++) {
        int col = coff + n * 8 + t * 2;
        *(uint32_t*)&g_ah[r0 * CC + col] =
            pack_hi(oacc[n][0] * inv0, oacc[n][1] * inv0);
        *(uint32_t*)&g_ah[(r0 + 8) * CC + col] =
            pack_hi(oacc[n][2] * inv1, oacc[n][3] * inv1);
    }
}

// ---------------------------------------------------------------------------
extern "C" void kernel_launch(void* const* d_in, const int* in_sizes, int n_in,
                              void* d_out, int out_size)
{
    const float* x    = (const float*)d_in[0];
    const float* Wqkv = (const float*)d_in[1];
    const float* Wo   = (const float*)d_in[2];
    float* out        = (float*)d_out;

    __half *xh, *wqh, *woh, *ah;
    cudaGetSymbolAddress((void**)&xh, g_xh);
    cudaGetSymbolAddress((void**)&wqh, g_wqh);
    cudaGetSymbolAddress((void**)&woh, g_woh);
    cudaGetSymbolAddress((void**)&ah, g_ah);

    cudaFuncSetAttribute(gemm_f16x1_kernel<0>,
                         cudaFuncAttributeMaxDynamicSharedMemorySize, GEMM_SMEM);
    cudaFuncSetAttribute(gemm_f16x1_kernel<1>,
                         cudaFuncAttributeMaxDynamicSharedMemorySize, GEMM_SMEM);
    cudaFuncSetAttribute(attn_mma_kernel,
                         cudaFuncAttributeMaxDynamicSharedMemorySize, ATT_SMEM);

    // merged hi-only conversion (x | Wqkv | Wo)
    cvt_all_kernel<<<(N4_ALL + 255)/256, 256>>>(
        (const float4*)x, (const float4*)Wqkv, (const float4*)Wo);

    // 1) qkv projection (1-product); epilogue: q split+scaled, k/v hi only
    {
        dim3 grid(C3 / 64, BT / 128);
        gemm_f16x1_kernel<1><<<grid, 256, GEMM_SMEM>>>(
            xh, wqh, (float*)nullptr, BT, C3, CC);
    }
    // 2) causal flash attention (2-product core)
    {
        dim3 grid(TT / 128, BB * HH);
        attn_mma_kernel<<<grid, 256, ATT_SMEM>>>();
    }
    // 3) out = att @ Wo^T (1-product, fp32 result)
    {
        dim3 grid(CC / 64, BT / 128);
        gemm_f16x1_kernel<0><<<grid, 256, GEMM_SMEM>>>(
            ah, woh, out, BT, CC, CC);
    }
}

// round 16
// speedup vs baseline: 2.1392x; 1.1068x over previous
#include <cuda_runtime.h>
#include <cuda_fp16.h>
#include <cstdint>
#include <cstddef>

// Problem constants
#define BB 4
#define TT 2048
#define CC 1024
#define HH 16
#define DK 64
#define BT (BB*TT)        // 8192
#define C3 (3*CC)         // 3072

// ---------------------------------------------------------------------------
// Scratch (allocation-free rule: device globals)
// ---------------------------------------------------------------------------
__device__ __half g_xh[(size_t)BT * CC];           // x hi
__device__ __half g_wqh[(size_t)C3 * CC];          // Wqkv hi
__device__ __half g_woh[(size_t)CC * CC];          // Wo hi
// attention operands (GEMM1 epilogue): q split+scaled, k/v hi only
__device__ __half g_qh[(size_t)BT * CC],  g_ql[(size_t)BT * CC];
__device__ __half g_kh[(size_t)BT * CC];
__device__ __half g_vh[(size_t)BT * CC];
// attention output, hi only (A-operand of GEMM2)
__device__ __half g_ah[(size_t)BT * CC];

extern __shared__ char dynsm[];

__device__ __forceinline__ uint32_t smem_to_u32(const void* p) {
    uint32_t a;
    asm("{ .reg .u64 t; cvta.to.shared.u64 t, %1; cvt.u32.u64 %0, t; }"
        : "=r"(a) : "l"(p));
    return a;
}
__device__ __forceinline__ void mma_f16(float* c, const uint32_t* a, const uint32_t* b) {
    asm volatile("mma.sync.aligned.m16n8k16.row.col.f32.f16.f16.f32 "
        "{%0,%1,%2,%3}, {%4,%5,%6,%7}, {%8,%9}, {%0,%1,%2,%3};"
        : "+f"(c[0]), "+f"(c[1]), "+f"(c[2]), "+f"(c[3])
        : "r"(a[0]), "r"(a[1]), "r"(a[2]), "r"(a[3]), "r"(b[0]), "r"(b[1]));
}
__device__ __forceinline__ void ldsm_x4(uint32_t* r, uint32_t addr) {
    asm volatile("ldmatrix.sync.aligned.m8n8.x4.shared.b16 {%0,%1,%2,%3}, [%4];"
        : "=r"(r[0]), "=r"(r[1]), "=r"(r[2]), "=r"(r[3]) : "r"(addr));
}
__device__ __forceinline__ void ldsm_x2(uint32_t* r, uint32_t addr) {
    asm volatile("ldmatrix.sync.aligned.m8n8.x2.shared.b16 {%0,%1}, [%2];"
        : "=r"(r[0]), "=r"(r[1]) : "r"(addr));
}
__device__ __forceinline__ void ldsm_x2_trans(uint32_t* r, uint32_t addr) {
    asm volatile("ldmatrix.sync.aligned.m8n8.x2.trans.shared.b16 {%0,%1}, [%2];"
        : "=r"(r[0]), "=r"(r[1]) : "r"(addr));
}
#define CP_ASYNC16(dst, src) \
    asm volatile("cp.async.cg.shared.global [%0], [%1], 16;" :: "r"(dst), "l"(src))
#define CP_COMMIT()  asm volatile("cp.async.commit_group;" ::: "memory")
#define CP_WAIT1()   asm volatile("cp.async.wait_group 1;" ::: "memory")

__device__ __forceinline__ void split2(float a, float b, uint32_t& h, uint32_t& l) {
    __half ha = __float2half_rn(a), hb = __float2half_rn(b);
    __half la = __float2half_rn(a - __half2float(ha));
    __half lb = __float2half_rn(b - __half2float(hb));
    __half2 hp = __halves2half2(ha, hb);
    __half2 lp = __halves2half2(la, lb);
    h = *(uint32_t*)&hp; l = *(uint32_t*)&lp;
}
__device__ __forceinline__ uint32_t pack_hi(float a, float b) {
    __half2 hp = __halves2half2(__float2half_rn(a), __float2half_rn(b));
    return *(uint32_t*)&hp;
}

// ---------------------------------------------------------------------------
// Merged conversion: x, Wqkv, Wo -> fp16 hi only
// ---------------------------------------------------------------------------
#define N4_X   (BT * CC / 4)
#define N4_WQ  (C3 * CC / 4)
#define N4_WO  (CC * CC / 4)
#define N4_ALL (N4_X + N4_WQ + N4_WO)

__global__ void cvt_all_kernel(const float4* __restrict__ x,
                               const float4* __restrict__ wq,
                               const float4* __restrict__ wo)
{
    int i = blockIdx.x * blockDim.x + threadIdx.x;
    if (i >= N4_ALL) return;
    const float4* src;
    uint32_t* dst;
    int j;
    if (i < N4_X)              { j = i;                src = x;  dst = (uint32_t*)g_xh; }
    else if (i < N4_X + N4_WQ) { j = i - N4_X;         src = wq; dst = (uint32_t*)g_wqh; }
    else                       { j = i - N4_X - N4_WQ; src = wo; dst = (uint32_t*)g_woh; }
    float4 v = src[j];
    dst[2*j]   = pack_hi(v.x, v.y);
    dst[2*j+1] = pack_hi(v.z, v.w);
}

// ---------------------------------------------------------------------------
// HMMA single-product fp16 GEMM: C = Ah @ Bh^T.
// CTA tile 128x128, 8 warps in 2x4 grid (64x32 warp tiles),
// 3-stage cp.async, 2 CTAs/SM.
// MODE 0: C fp32.  MODE 1: qkv epilogue (q split+scaled, k/v hi only).
// ---------------------------------------------------------------------------
#define RS_B     80
#define A_TILE_B (128*RS_B)         // 10240
#define B_TILE_B (128*RS_B)         // 10240
#define STAGE_B  (A_TILE_B + B_TILE_B)   // 20480
#define STAGES   3
#define GEMM_SMEM (STAGES*STAGE_B)  // 61440 (x2 CTAs = 122880)

template<int MODE>
__global__ __launch_bounds__(256, 2) void gemm_f16x1_kernel(
    const __half* __restrict__ Ah, const __half* __restrict__ Bh,
    float* __restrict__ C, int M, int N, int K)
{
    const int tid = threadIdx.x, lane = tid & 31, wid = tid >> 5;
    const int bm = blockIdx.y * 128, bn = blockIdx.x * 128;
    const int wr = wid >> 2, wc = wid & 3;     // 2x4 warp grid, 64x32 tiles
    const uint32_t sbase = smem_to_u32(dynsm);
    const int NC = K / 32;

    float acc[4][4][4];
#pragma unroll
    for (int i = 0; i < 4; i++)
#pragma unroll
        for (int j = 0; j < 4; j++)
#pragma unroll
            for (int v = 0; v < 4; v++) acc[i][j][v] = 0.0f;

    // 1024 16B-chunks per stage: Ah 512, Bh 512. 4 per thread.
    auto load_stage = [&](int st, int buf) {
        const int kk = st * 32;
        const uint32_t dstb = sbase + buf * STAGE_B;
#pragma unroll
        for (int i = 0; i < 4; i++) {
            int c = tid + i * 256;                 // 0..1023
            const __half* src;
            uint32_t dst;
            if (c < 512) {
                int row = c >> 2, kc = c & 3;
                src = Ah + (size_t)(bm + row) * K + kk + kc * 8;
                dst = dstb + row * RS_B + kc * 16;
            } else {
                int cb = c - 512;
                int row = cb >> 2, kc = cb & 3;
                src = Bh + (size_t)(bn + row) * K + kk + kc * 8;
                dst = dstb + A_TILE_B + row * RS_B + kc * 16;
            }
            CP_ASYNC16(dst, src);
        }
    };

    const uint32_t a_off0 = (wr * 64 + (lane & 15)) * RS_B + (lane >> 4) * 16;
    const uint32_t b_off0 = (wc * 32 + (lane & 7)) * RS_B + ((lane >> 3) & 1) * 16;

    load_stage(0, 0); CP_COMMIT();
    load_stage(1, 1); CP_COMMIT();

    for (int it = 0; it < NC; it++) {
        CP_WAIT1();
        __syncthreads();
        const int nxt = it + (STAGES - 1);
        if (nxt < NC) load_stage(nxt, nxt % STAGES);
        CP_COMMIT();

        const uint32_t tb = sbase + (it % STAGES) * STAGE_B;
#pragma unroll
        for (int ks = 0; ks < 2; ks++) {
            uint32_t ah[4][4], bh[4][2];
#pragma unroll
            for (int mt = 0; mt < 4; mt++)
                ldsm_x4(ah[mt], tb + a_off0 + mt * (16 * RS_B) + ks * 32);
#pragma unroll
            for (int nt = 0; nt < 4; nt++)
                ldsm_x2(bh[nt], tb + A_TILE_B + b_off0 + nt * (8 * RS_B) + ks * 32);
#pragma unroll
            for (int mt = 0; mt < 4; mt++)
#pragma unroll
                for (int nt = 0; nt < 4; nt++) mma_f16(acc[mt][nt], ah[mt], bh[nt]);
        }
    }

    // epilogue
    const int g = lane >> 2, t = lane & 3;
#pragma unroll
    for (int mt = 0; mt < 4; mt++) {
#pragma unroll
        for (int nt = 0; nt < 4; nt++) {
            int row = bm + wr * 64 + mt * 16 + g;
            int col = bn + wc * 32 + nt * 8 + t * 2;
            if (MODE == 0) {
                *(float2*)&C[(size_t)row * N + col] =
                    make_float2(acc[mt][nt][0], acc[mt][nt][1]);
                *(float2*)&C[(size_t)(row + 8) * N + col] =
                    make_float2(acc[mt][nt][2], acc[mt][nt][3]);
            } else {
                if (bn < CC) {                     // q: scale, split
                    uint32_t h0, l0, h1, l1;
                    split2(acc[mt][nt][0]*0.125f, acc[mt][nt][1]*0.125f, h0, l0);
                    split2(acc[mt][nt][2]*0.125f, acc[mt][nt][3]*0.125f, h1, l1);
                    *(uint32_t*)&g_qh[(size_t)row * CC + col]       = h0;
                    *(uint32_t*)&g_ql[(size_t)row * CC + col]       = l0;
                    *(uint32_t*)&g_qh[(size_t)(row + 8) * CC + col] = h1;
                    *(uint32_t*)&g_ql[(size_t)(row + 8) * CC + col] = l1;
                } else if (bn < 2 * CC) {          // k: hi only
                    int cc = col - CC;
                    *(uint32_t*)&g_kh[(size_t)row * CC + cc] =
                        pack_hi(acc[mt][nt][0], acc[mt][nt][1]);
                    *(uint32_t*)&g_kh[(size_t)(row + 8) * CC + cc] =
                        pack_hi(acc[mt][nt][2], acc[mt][nt][3]);
                } else {                            // v: hi only
                    int cc = col - 2 * CC;
                    *(uint32_t*)&g_vh[(size_t)row * CC + cc] =
                        pack_hi(acc[mt][nt][0], acc[mt][nt][1]);
                    *(uint32_t*)&g_vh[(size_t)(row + 8) * CC + cc] =
                        pack_hi(acc[mt][nt][2], acc[mt][nt][3]);
                }
            }
        }
    }
}

// ---------------------------------------------------------------------------
// HMMA 2-product flash attention, causal (unchanged from R12).
// ---------------------------------------------------------------------------
#define RSA   144
#define QREG  18432                 // 128*144
#define SBUF  (2*QREG)              // 36864
#define SSZ   18432                 // KH + VH @ 9216 each
#define ATT_SMEM (SBUF + 2*SSZ)     // 73728

__global__ __launch_bounds__(256, 1) void attn_mma_kernel()
{
    const uint32_t sbase = smem_to_u32(dynsm);
    const int tid = threadIdx.x, lane = tid & 31, w = tid >> 5;
    const int qb = gridDim.x - 1 - blockIdx.x;   // heavy blocks first
    const int b  = blockIdx.y >> 4;
    const int h  = blockIdx.y & 15;
    const size_t rbase = (size_t)b * TT;
    const int coff = h * DK;
    const int g = lane >> 2, t = lane & 3;

    // ---- stage Q (hi+lo) via cp.async ----
#pragma unroll
    for (int i = 0; i < 8; i++) {
        int idx = tid + i * 256;              // 0..2047
        int arr = idx >> 10;                  // 0: qh, 1: ql
        int rem = idx & 1023;
        int r = rem >> 3, c = rem & 7;
        const __half* src =
            (arr ? g_ql : g_qh) + (rbase + (size_t)qb * 128 + r) * CC + coff + c * 8;
        uint32_t dst = sbase + arr * QREG + r * RSA + c * 16;
        CP_ASYNC16(dst, src);
    }

    auto load_stage = [&](int jb, int s) {
        const uint32_t dstb = sbase + SBUF + s * SSZ;
#pragma unroll
        for (int i = 0; i < 4; i++) {
            int idx = tid + i * 256;          // 0..1023
            int sub = idx >> 9;               // 0:KH 1:VH
            int rem = idx & 511;
            int r = rem >> 3, c = rem & 7;
            const __half* base = sub ? g_vh : g_kh;
            const __half* src = base + (rbase + (size_t)jb * 64 + r) * CC + coff + c * 8;
            uint32_t dst = dstb + sub * 9216 + r * RSA + c * 16;
            CP_ASYNC16(dst, src);
        }
    };

    const int jb_end = 2 * qb + 1;
    load_stage(0, 0);
    CP_COMMIT();            // group: Q + stage0

    float oacc[8][4];
#pragma unroll
    for (int n = 0; n < 8; n++)
#pragma unroll
        for (int v = 0; v < 4; v++) oacc[n][v] = 0.0f;
    float m0 = -1e30f, m1 = -1e30f, l0s = 0.0f, l1s = 0.0f;
    uint32_t qh[4][4], ql[4][4];

    const int qrow0 = qb * 128 + w * 16 + g;

    for (int jb = 0; jb <= jb_end; jb++) {
        const int buf = jb & 1;
        if (jb + 1 <= jb_end) load_stage(jb + 1, buf ^ 1);
        CP_COMMIT();
        CP_WAIT1();
        __syncthreads();

        if (jb == 0) {   // Q fragments (once)
#pragma unroll
            for (int kt = 0; kt < 4; kt++) {
                uint32_t addr = sbase + (w * 16 + (lane & 15)) * RSA
                              + (lane >> 4) * 16 + kt * 32;
                ldsm_x4(qh[kt], addr);
                ldsm_x4(ql[kt], addr + QREG);
            }
        }

        const uint32_t KhB = sbase + SBUF + buf * SSZ;
        const uint32_t VhB = KhB + 9216;

        const bool active = (jb * 64 <= qb * 128 + w * 16 + 15);
        if (active) {
            // ---- S = Q K^T (2 products) ----
            float sacc[8][4];
#pragma unroll
            for (int n = 0; n < 8; n++)
#pragma unroll
                for (int v = 0; v < 4; v++) sacc[n][v] = 0.0f;
#pragma unroll
            for (int kt = 0; kt < 4; kt++) {
                uint32_t bh[8][2];
#pragma unroll
                for (int n = 0; n < 8; n++) {
                    uint32_t baddr = (n * 8 + (lane & 7)) * RSA + kt * 32
                                   + ((lane >> 3) & 1) * 16;
                    ldsm_x2(bh[n], KhB + baddr);
                }
#pragma unroll
                for (int n = 0; n < 8; n++) mma_f16(sacc[n], qh[kt], bh[n]);
#pragma unroll
                for (int n = 0; n < 8; n++) mma_f16(sacc[n], ql[kt], bh[n]);
            }

            // ---- causal mask ----
            if (jb * 64 + 63 > qrow0) {
#pragma unroll
                for (int n = 0; n < 8; n++) {
                    int colb = jb * 64 + n * 8 + t * 2;
                    if (colb     > qrow0)     sacc[n][0] = -1e30f;
                    if (colb + 1 > qrow0)     sacc[n][1] = -1e30f;
                    if (colb     > qrow0 + 8) sacc[n][2] = -1e30f;
                    if (colb + 1 > qrow0 + 8) sacc[n][3] = -1e30f;
                }
            }

            // ---- online softmax ----
            float rmax0 = -1e30f, rmax1 = -1e30f;
#pragma unroll
            for (int n = 0; n < 8; n++) {
                rmax0 = fmaxf(rmax0, fmaxf(sacc[n][0], sacc[n][1]));
                rmax1 = fmaxf(rmax1, fmaxf(sacc[n][2], sacc[n][3]));
            }
            rmax0 = fmaxf(rmax0, __shfl_xor_sync(0xffffffffu, rmax0, 1));
            rmax0 = fmaxf(rmax0, __shfl_xor_sync(0xffffffffu, rmax0, 2));
            rmax1 = fmaxf(rmax1, __shfl_xor_sync(0xffffffffu, rmax1, 1));
            rmax1 = fmaxf(rmax1, __shfl_xor_sync(0xffffffffu, rmax1, 2));

            const float mn0 = fmaxf(m0, rmax0), mn1 = fmaxf(m1, rmax1);
            const float c0 = __expf(m0 - mn0), c1 = __expf(m1 - mn1);
            float rs0 = 0.0f, rs1 = 0.0f;
#pragma unroll
            for (int n = 0; n < 8; n++) {
                sacc[n][0] = __expf(sacc[n][0] - mn0);
                sacc[n][1] = __expf(sacc[n][1] - mn0);
                sacc[n][2] = __expf(sacc[n][2] - mn1);
                sacc[n][3] = __expf(sacc[n][3] - mn1);
                rs0 += sacc[n][0] + sacc[n][1];
                rs1 += sacc[n][2] + sacc[n][3];
            }
            rs0 += __shfl_xor_sync(0xffffffffu, rs0, 1);
            rs0 += __shfl_xor_sync(0xffffffffu, rs0, 2);
            rs1 += __shfl_xor_sync(0xffffffffu, rs1, 1);
            rs1 += __shfl_xor_sync(0xffffffffu, rs1, 2);
            l0s = l0s * c0 + rs0; l1s = l1s * c1 + rs1;
            m0 = mn0; m1 = mn1;
#pragma unroll
            for (int n = 0; n < 8; n++) {
                oacc[n][0] *= c0; oacc[n][1] *= c0;
                oacc[n][2] *= c1; oacc[n][3] *= c1;
            }

            // ---- O += P V (2 products); V via trans-ldsm ----
#pragma unroll
            for (int kt = 0; kt < 4; kt++) {
                uint32_t pah[4], pal[4];
                split2(sacc[2*kt][0],   sacc[2*kt][1],   pah[0], pal[0]);
                split2(sacc[2*kt][2],   sacc[2*kt][3],   pah[1], pal[1]);
                split2(sacc[2*kt+1][0], sacc[2*kt+1][1], pah[2], pal[2]);
                split2(sacc[2*kt+1][2], sacc[2*kt+1][3], pah[3], pal[3]);
                const uint32_t vrow = (kt * 16 + (lane & 15)) * RSA;
                uint32_t bvh[8][2];
#pragma unroll
                for (int n = 0; n < 8; n++)
                    ldsm_x2_trans(bvh[n], VhB + vrow + n * 16);
#pragma unroll
                for (int n = 0; n < 8; n++) mma_f16(oacc[n], pah, bvh[n]);
#pragma unroll
                for (int n = 0; n < 8; n++) mma_f16(oacc[n], pal, bvh[n]);
            }
        }
        __syncthreads();   // buffer consumed before next prefetch overwrites
    }

    // ---- epilogue: normalize, store fp16 hi ----
    const float inv0 = 1.0f / l0s, inv1 = 1.0f / l1s;
    const size_t r0 = rbase + (size_t)qb * 128 + w * 16 + g;
#pragma unroll
    for (int n = 0; n < 8; n++) {
        int col = coff + n * 8 + t * 2;
        *(uint32_t*)&g_ah[r0 * CC + col] =
            pack_hi(oacc[n][0] * inv0, oacc[n][1] * inv0);
        *(uint32_t*)&g_ah[(r0 + 8) * CC + col] =
            pack_hi(oacc[n][2] * inv1, oacc[n][3] * inv1);
    }
}

// ---------------------------------------------------------------------------
extern "C" void kernel_launch(void* const* d_in, const int* in_sizes, int n_in,
                              void* d_out, int out_size)
{
    const float* x    = (const float*)d_in[0];
    const float* Wqkv = (const float*)d_in[1];
    const float* Wo   = (const float*)d_in[2];
    float* out        = (float*)d_out;

    __half *xh, *wqh, *woh, *ah;
    cudaGetSymbolAddress((void**)&xh, g_xh);
    cudaGetSymbolAddress((void**)&wqh, g_wqh);
    cudaGetSymbolAddress((void**)&woh, g_woh);
    cudaGetSymbolAddress((void**)&ah, g_ah);

    cudaFuncSetAttribute(gemm_f16x1_kernel<0>,
                         cudaFuncAttributeMaxDynamicSharedMemorySize, GEMM_SMEM);
    cudaFuncSetAttribute(gemm_f16x1_kernel<1>,
                         cudaFuncAttributeMaxDynamicSharedMemorySize, GEMM_SMEM);
    cudaFuncSetAttribute(attn_mma_kernel,
                         cudaFuncAttributeMaxDynamicSharedMemorySize, ATT_SMEM);

    // merged hi-only conversion (x | Wqkv | Wo)
    cvt_all_kernel<<<(N4_ALL + 255)/256, 256>>>(
        (const float4*)x, (const float4*)Wqkv, (const float4*)Wo);

    // 1) qkv projection (1-product); epilogue: q split+scaled, k/v hi only
    {
        dim3 grid(C3 / 128, BT / 128);
        gemm_f16x1_kernel<1><<<grid, 256, GEMM_SMEM>>>(
            xh, wqh, (float*)nullptr, BT, C3, CC);
    }
    // 2) causal flash attention (2-product core)
    {
        dim3 grid(TT / 128, BB * HH);
        attn_mma_kernel<<<grid, 256, ATT_SMEM>>>();
    }
    // 3) out = att @ Wo^T (1-product, fp32 result)
    {
        dim3 grid(CC / 128, BT / 128);
        gemm_f16x1_kernel<0><<<grid, 256, GEMM_SMEM>>>(
            ah, woh, out, BT, CC, CC);
    }
}

// round 17
// speedup vs baseline: 2.6023x; 1.2165x over previous
#include <cuda_runtime.h>
#include <cuda_fp16.h>
#include <cstdint>
#include <cstddef>

// Problem constants
#define BB 4
#define TT 2048
#define CC 1024
#define HH 16
#define DK 64
#define BT (BB*TT)        // 8192
#define C3 (3*CC)         // 3072

// ---------------------------------------------------------------------------
// Scratch (allocation-free rule: device globals)
// ---------------------------------------------------------------------------
__device__ __half g_xh[(size_t)BT * CC];           // x hi
__device__ __half g_wqh[(size_t)C3 * CC];          // Wqkv hi
__device__ __half g_woh[(size_t)CC * CC];          // Wo hi
// attention operands (GEMM1 epilogue): all hi-only, q pre-scaled
__device__ __half g_qh[(size_t)BT * CC];
__device__ __half g_kh[(size_t)BT * CC];
__device__ __half g_vh[(size_t)BT * CC];
// attention output, hi only (A-operand of GEMM2)
__device__ __half g_ah[(size_t)BT * CC];

extern __shared__ char dynsm[];

__device__ __forceinline__ uint32_t smem_to_u32(const void* p) {
    uint32_t a;
    asm("{ .reg .u64 t; cvta.to.shared.u64 t, %1; cvt.u32.u64 %0, t; }"
        : "=r"(a) : "l"(p));
    return a;
}
__device__ __forceinline__ void mma_f16(float* c, const uint32_t* a, const uint32_t* b) {
    asm volatile("mma.sync.aligned.m16n8k16.row.col.f32.f16.f16.f32 "
        "{%0,%1,%2,%3}, {%4,%5,%6,%7}, {%8,%9}, {%0,%1,%2,%3};"
        : "+f"(c[0]), "+f"(c[1]), "+f"(c[2]), "+f"(c[3])
        : "r"(a[0]), "r"(a[1]), "r"(a[2]), "r"(a[3]), "r"(b[0]), "r"(b[1]));
}
__device__ __forceinline__ void ldsm_x4(uint32_t* r, uint32_t addr) {
    asm volatile("ldmatrix.sync.aligned.m8n8.x4.shared.b16 {%0,%1,%2,%3}, [%4];"
        : "=r"(r[0]), "=r"(r[1]), "=r"(r[2]), "=r"(r[3]) : "r"(addr));
}
__device__ __forceinline__ void ldsm_x2(uint32_t* r, uint32_t addr) {
    asm volatile("ldmatrix.sync.aligned.m8n8.x2.shared.b16 {%0,%1}, [%2];"
        : "=r"(r[0]), "=r"(r[1]) : "r"(addr));
}
__device__ __forceinline__ void ldsm_x2_trans(uint32_t* r, uint32_t addr) {
    asm volatile("ldmatrix.sync.aligned.m8n8.x2.trans.shared.b16 {%0,%1}, [%2];"
        : "=r"(r[0]), "=r"(r[1]) : "r"(addr));
}
#define CP_ASYNC16(dst, src) \
    asm volatile("cp.async.cg.shared.global [%0], [%1], 16;" :: "r"(dst), "l"(src))
#define CP_COMMIT()  asm volatile("cp.async.commit_group;" ::: "memory")
#define CP_WAIT1()   asm volatile("cp.async.wait_group 1;" ::: "memory")

__device__ __forceinline__ uint32_t pack_hi(float a, float b) {
    __half2 hp = __halves2half2(__float2half_rn(a), __float2half_rn(b));
    return *(uint32_t*)&hp;
}

// ---------------------------------------------------------------------------
// Merged conversion: x, Wqkv, Wo -> fp16 hi only
// ---------------------------------------------------------------------------
#define N4_X   (BT * CC / 4)
#define N4_WQ  (C3 * CC / 4)
#define N4_WO  (CC * CC / 4)
#define N4_ALL (N4_X + N4_WQ + N4_WO)

__global__ void cvt_all_kernel(const float4* __restrict__ x,
                               const float4* __restrict__ wq,
                               const float4* __restrict__ wo)
{
    int i = blockIdx.x * blockDim.x + threadIdx.x;
    if (i >= N4_ALL) return;
    const float4* src;
    uint32_t* dst;
    int j;
    if (i < N4_X)              { j = i;                src = x;  dst = (uint32_t*)g_xh; }
    else if (i < N4_X + N4_WQ) { j = i - N4_X;         src = wq; dst = (uint32_t*)g_wqh; }
    else                       { j = i - N4_X - N4_WQ; src = wo; dst = (uint32_t*)g_woh; }
    float4 v = src[j];
    dst[2*j]   = pack_hi(v.x, v.y);
    dst[2*j+1] = pack_hi(v.z, v.w);
}

// ---------------------------------------------------------------------------
// HMMA single-product fp16 GEMM: C = Ah @ Bh^T.
// CTA tile 128x128, 8 warps in 2x4 grid (64x32 warp tiles),
// 3-stage cp.async, 2 CTAs/SM.
// MODE 0: C fp32.  MODE 1: qkv epilogue (q scaled, all hi-only).
// ---------------------------------------------------------------------------
#define RS_B     80
#define A_TILE_B (128*RS_B)         // 10240
#define B_TILE_B (128*RS_B)         // 10240
#define STAGE_B  (A_TILE_B + B_TILE_B)   // 20480
#define STAGES   3
#define GEMM_SMEM (STAGES*STAGE_B)  // 61440 (x2 CTAs = 122880)

template<int MODE>
__global__ __launch_bounds__(256, 2) void gemm_f16x1_kernel(
    const __half* __restrict__ Ah, const __half* __restrict__ Bh,
    float* __restrict__ C, int M, int N, int K)
{
    const int tid = threadIdx.x, lane = tid & 31, wid = tid >> 5;
    const int bm = blockIdx.y * 128, bn = blockIdx.x * 128;
    const int wr = wid >> 2, wc = wid & 3;     // 2x4 warp grid, 64x32 tiles
    const uint32_t sbase = smem_to_u32(dynsm);
    const int NC = K / 32;

    float acc[4][4][4];
#pragma unroll
    for (int i = 0; i < 4; i++)
#pragma unroll
        for (int j = 0; j < 4; j++)
#pragma unroll
            for (int v = 0; v < 4; v++) acc[i][j][v] = 0.0f;

    auto load_stage = [&](int st, int buf) {
        const int kk = st * 32;
        const uint32_t dstb = sbase + buf * STAGE_B;
#pragma unroll
        for (int i = 0; i < 4; i++) {
            int c = tid + i * 256;                 // 0..1023
            const __half* src;
            uint32_t dst;
            if (c < 512) {
                int row = c >> 2, kc = c & 3;
                src = Ah + (size_t)(bm + row) * K + kk + kc * 8;
                dst = dstb + row * RS_B + kc * 16;
            } else {
                int cb = c - 512;
                int row = cb >> 2, kc = cb & 3;
                src = Bh + (size_t)(bn + row) * K + kk + kc * 8;
                dst = dstb + A_TILE_B + row * RS_B + kc * 16;
            }
            CP_ASYNC16(dst, src);
        }
    };

    const uint32_t a_off0 = (wr * 64 + (lane & 15)) * RS_B + (lane >> 4) * 16;
    const uint32_t b_off0 = (wc * 32 + (lane & 7)) * RS_B + ((lane >> 3) & 1) * 16;

    load_stage(0, 0); CP_COMMIT();
    load_stage(1, 1); CP_COMMIT();

    for (int it = 0; it < NC; it++) {
        CP_WAIT1();
        __syncthreads();
        const int nxt = it + (STAGES - 1);
        if (nxt < NC) load_stage(nxt, nxt % STAGES);
        CP_COMMIT();

        const uint32_t tb = sbase + (it % STAGES) * STAGE_B;
#pragma unroll
        for (int ks = 0; ks < 2; ks++) {
            uint32_t ah[4][4], bh[4][2];
#pragma unroll
            for (int mt = 0; mt < 4; mt++)
                ldsm_x4(ah[mt], tb + a_off0 + mt * (16 * RS_B) + ks * 32);
#pragma unroll
            for (int nt = 0; nt < 4; nt++)
                ldsm_x2(bh[nt], tb + A_TILE_B + b_off0 + nt * (8 * RS_B) + ks * 32);
#pragma unroll
            for (int mt = 0; mt < 4; mt++)
#pragma unroll
                for (int nt = 0; nt < 4; nt++) mma_f16(acc[mt][nt], ah[mt], bh[nt]);
        }
    }

    // epilogue
    const int g = lane >> 2, t = lane & 3;
#pragma unroll
    for (int mt = 0; mt < 4; mt++) {
#pragma unroll
        for (int nt = 0; nt < 4; nt++) {
            int row = bm + wr * 64 + mt * 16 + g;
            int col = bn + wc * 32 + nt * 8 + t * 2;
            if (MODE == 0) {
                *(float2*)&C[(size_t)row * N + col] =
                    make_float2(acc[mt][nt][0], acc[mt][nt][1]);
                *(float2*)&C[(size_t)(row + 8) * N + col] =
                    make_float2(acc[mt][nt][2], acc[mt][nt][3]);
            } else {
                float s = (bn < CC) ? 0.125f : 1.0f;   // q pre-scaled
                __half* dh;
                int cc;
                if (bn < CC)            { dh = g_qh; cc = col; }
                else if (bn < 2 * CC)   { dh = g_kh; cc = col - CC; }
                else                    { dh = g_vh; cc = col - 2 * CC; }
                *(uint32_t*)&dh[(size_t)row * CC + cc] =
                    pack_hi(acc[mt][nt][0] * s, acc[mt][nt][1] * s);
                *(uint32_t*)&dh[(size_t)(row + 8) * CC + cc] =
                    pack_hi(acc[mt][nt][2] * s, acc[mt][nt][3] * s);
            }
        }
    }
}

// ---------------------------------------------------------------------------
// HMMA single-product flash attention, causal. Q/K/V/P all hi-only fp16.
// CTA = 128 queries x (b,h); 8 warps x 16 rows; 64-key double-buffered tiles.
// 2 CTAs/SM. Heavy q-blocks launch first.
// ---------------------------------------------------------------------------
#define RSA   144
#define QREG  18432                 // 128*144 (single Q array)
#define SBUF  QREG                  // stage area start
#define SSZ   18432                 // KH + VH @ 9216 each
#define ATT_SMEM (SBUF + 2*SSZ)     // 55296 (x2 CTAs = 110592)

__global__ __launch_bounds__(256, 2) void attn_mma_kernel()
{
    const uint32_t sbase = smem_to_u32(dynsm);
    const int tid = threadIdx.x, lane = tid & 31, w = tid >> 5;
    const int qb = gridDim.x - 1 - blockIdx.x;   // heavy blocks first
    const int b  = blockIdx.y >> 4;
    const int h  = blockIdx.y & 15;
    const size_t rbase = (size_t)b * TT;
    const int coff = h * DK;
    const int g = lane >> 2, t = lane & 3;

    // ---- stage Q (hi) via cp.async: 1024 chunks, 4/thread ----
#pragma unroll
    for (int i = 0; i < 4; i++) {
        int idx = tid + i * 256;              // 0..1023
        int r = idx >> 3, c = idx & 7;
        const __half* src =
            g_qh + (rbase + (size_t)qb * 128 + r) * CC + coff + c * 8;
        uint32_t dst = sbase + r * RSA + c * 16;
        CP_ASYNC16(dst, src);
    }

    auto load_stage = [&](int jb, int s) {
        const uint32_t dstb = sbase + SBUF + s * SSZ;
#pragma unroll
        for (int i = 0; i < 4; i++) {
            int idx = tid + i * 256;          // 0..1023
            int sub = idx >> 9;               // 0:KH 1:VH
            int rem = idx & 511;
            int r = rem >> 3, c = rem & 7;
            const __half* base = sub ? g_vh : g_kh;
            const __half* src = base + (rbase + (size_t)jb * 64 + r) * CC + coff + c * 8;
            uint32_t dst = dstb + sub * 9216 + r * RSA + c * 16;
            CP_ASYNC16(dst, src);
        }
    };

    const int jb_end = 2 * qb + 1;
    load_stage(0, 0);
    CP_COMMIT();            // group: Q + stage0

    float oacc[8][4];
#pragma unroll
    for (int n = 0; n < 8; n++)
#pragma unroll
        for (int v = 0; v < 4; v++) oacc[n][v] = 0.0f;
    float m0 = -1e30f, m1 = -1e30f, l0s = 0.0f, l1s = 0.0f;
    uint32_t qh[4][4];

    const int qrow0 = qb * 128 + w * 16 + g;

    for (int jb = 0; jb <= jb_end; jb++) {
        const int buf = jb & 1;
        if (jb + 1 <= jb_end) load_stage(jb + 1, buf ^ 1);
        CP_COMMIT();
        CP_WAIT1();
        __syncthreads();

        if (jb == 0) {   // Q fragments (once)
#pragma unroll
            for (int kt = 0; kt < 4; kt++) {
                uint32_t addr = sbase + (w * 16 + (lane & 15)) * RSA
                              + (lane >> 4) * 16 + kt * 32;
                ldsm_x4(qh[kt], addr);
            }
        }

        const uint32_t KhB = sbase + SBUF + buf * SSZ;
        const uint32_t VhB = KhB + 9216;

        const bool active = (jb * 64 <= qb * 128 + w * 16 + 15);
        if (active) {
            // ---- S = Q K^T (single product) ----
            float sacc[8][4];
#pragma unroll
            for (int n = 0; n < 8; n++)
#pragma unroll
                for (int v = 0; v < 4; v++) sacc[n][v] = 0.0f;
#pragma unroll
            for (int kt = 0; kt < 4; kt++) {
                uint32_t bh[8][2];
#pragma unroll
                for (int n = 0; n < 8; n++) {
                    uint32_t baddr = (n * 8 + (lane & 7)) * RSA + kt * 32
                                   + ((lane >> 3) & 1) * 16;
                    ldsm_x2(bh[n], KhB + baddr);
                }
#pragma unroll
                for (int n = 0; n < 8; n++) mma_f16(sacc[n], qh[kt], bh[n]);
            }

            // ---- causal mask ----
            if (jb * 64 + 63 > qrow0) {
#pragma unroll
                for (int n = 0; n < 8; n++) {
                    int colb = jb * 64 + n * 8 + t * 2;
                    if (colb     > qrow0)     sacc[n][0] = -1e30f;
                    if (colb + 1 > qrow0)     sacc[n][1] = -1e30f;
                    if (colb     > qrow0 + 8) sacc[n][2] = -1e30f;
                    if (colb + 1 > qrow0 + 8) sacc[n][3] = -1e30f;
                }
            }

            // ---- online softmax ----
            float rmax0 = -1e30f, rmax1 = -1e30f;
#pragma unroll
            for (int n = 0; n < 8; n++) {
                rmax0 = fmaxf(rmax0, fmaxf(sacc[n][0], sacc[n][1]));
                rmax1 = fmaxf(rmax1, fmaxf(sacc[n][2], sacc[n][3]));
            }
            rmax0 = fmaxf(rmax0, __shfl_xor_sync(0xffffffffu, rmax0, 1));
            rmax0 = fmaxf(rmax0, __shfl_xor_sync(0xffffffffu, rmax0, 2));
            rmax1 = fmaxf(rmax1, __shfl_xor_sync(0xffffffffu, rmax1, 1));
            rmax1 = fmaxf(rmax1, __shfl_xor_sync(0xffffffffu, rmax1, 2));

            const float mn0 = fmaxf(m0, rmax0), mn1 = fmaxf(m1, rmax1);
            const float c0 = __expf(m0 - mn0), c1 = __expf(m1 - mn1);
            float rs0 = 0.0f, rs1 = 0.0f;
#pragma unroll
            for (int n = 0; n < 8; n++) {
                sacc[n][0] = __expf(sacc[n][0] - mn0);
                sacc[n][1] = __expf(sacc[n][1] - mn0);
                sacc[n][2] = __expf(sacc[n][2] - mn1);
                sacc[n][3] = __expf(sacc[n][3] - mn1);
                rs0 += sacc[n][0] + sacc[n][1];
                rs1 += sacc[n][2] + sacc[n][3];
            }
            rs0 += __shfl_xor_sync(0xffffffffu, rs0, 1);
            rs0 += __shfl_xor_sync(0xffffffffu, rs0, 2);
            rs1 += __shfl_xor_sync(0xffffffffu, rs1, 1);
            rs1 += __shfl_xor_sync(0xffffffffu, rs1, 2);
            l0s = l0s * c0 + rs0; l1s = l1s * c1 + rs1;
            m0 = mn0; m1 = mn1;
#pragma unroll
            for (int n = 0; n < 8; n++) {
                oacc[n][0] *= c0; oacc[n][1] *= c0;
                oacc[n][2] *= c1; oacc[n][3] *= c1;
            }

            // ---- O += P V (single product); V via trans-ldsm ----
#pragma unroll
            for (int kt = 0; kt < 4; kt++) {
                uint32_t pah[4];
                pah[0] = pack_hi(sacc[2*kt][0],   sacc[2*kt][1]);
                pah[1] = pack_hi(sacc[2*kt][2],   sacc[2*kt][3]);
                pah[2] = pack_hi(sacc[2*kt+1][0], sacc[2*kt+1][1]);
                pah[3] = pack_hi(sacc[2*kt+1][2], sacc[2*kt+1][3]);
                const uint32_t vrow = (kt * 16 + (lane & 15)) * RSA;
                uint32_t bvh[8][2];
#pragma unroll
                for (int n = 0; n < 8; n++)
                    ldsm_x2_trans(bvh[n], VhB + vrow + n * 16);
#pragma unroll
                for (int n = 0; n < 8; n++) mma_f16(oacc[n], pah, bvh[n]);
            }
        }
        __syncthreads();   // buffer consumed before next prefetch overwrites
    }

    // ---- epilogue: normalize, store fp16 hi ----
    const float inv0 = 1.0f / l0s, inv1 = 1.0f / l1s;
    const size_t r0 = rbase + (size_t)qb * 128 + w * 16 + g;
#pragma unroll
    for (int n = 0; n < 8; n++) {
        int col = coff + n * 8 + t * 2;
        *(uint32_t*)&g_ah[r0 * CC + col] =
            pack_hi(oacc[n][0] * inv0, oacc[n][1] * inv0);
        *(uint32_t*)&g_ah[(r0 + 8) * CC + col] =
            pack_hi(oacc[n][2] * inv1, oacc[n][3] * inv1);
    }
}

// ---------------------------------------------------------------------------
extern "C" void kernel_launch(void* const* d_in, const int* in_sizes, int n_in,
                              void* d_out, int out_size)
{
    const float* x    = (const float*)d_in[0];
    const float* Wqkv = (const float*)d_in[1];
    const float* Wo   = (const float*)d_in[2];
    float* out        = (float*)d_out;

    __half *xh, *wqh, *woh, *ah;
    cudaGetSymbolAddress((void**)&xh, g_xh);
    cudaGetSymbolAddress((void**)&wqh, g_wqh);
    cudaGetSymbolAddress((void**)&woh, g_woh);
    cudaGetSymbolAddress((void**)&ah, g_ah);

    cudaFuncSetAttribute(gemm_f16x1_kernel<0>,
                         cudaFuncAttributeMaxDynamicSharedMemorySize, GEMM_SMEM);
    cudaFuncSetAttribute(gemm_f16x1_kernel<1>,
                         cudaFuncAttributeMaxDynamicSharedMemorySize, GEMM_SMEM);
    cudaFuncSetAttribute(attn_mma_kernel,
                         cudaFuncAttributeMaxDynamicSharedMemorySize, ATT_SMEM);

    // merged hi-only conversion (x | Wqkv | Wo)
    cvt_all_kernel<<<(N4_ALL + 255)/256, 256>>>(
        (const float4*)x, (const float4*)Wqkv, (const float4*)Wo);

    // 1) qkv projection (1-product); epilogue: q scaled, all hi-only
    {
        dim3 grid(C3 / 128, BT / 128);
        gemm_f16x1_kernel<1><<<grid, 256, GEMM_SMEM>>>(
            xh, wqh, (float*)nullptr, BT, C3, CC);
    }
    // 2) causal flash attention (single-product, 2 CTAs/SM)
    {
        dim3 grid(TT / 128, BB * HH);
        attn_mma_kernel<<<grid, 256, ATT_SMEM>>>();
    }
    // 3) out = att @ Wo^T (1-product, fp32 result)
    {
        dim3 grid(CC / 128, BT / 128);
        gemm_f16x1_kernel<0><<<grid, 256, GEMM_SMEM>>>(
            ah, woh, out, BT, CC, CC);
    }
}